// round 3
// baseline (speedup 1.0000x reference)
#include <cuda_runtime.h>
#include <math_constants.h>

// Problem constants
#define NPTS 1024
#define DD   64
#define HA   256   // H_ATTN
// tile config
#define TJ   64    // j-tile
#define NT   256   // threads per CTA

// ---------------- device scratch (no runtime allocation allowed) ----------------
__device__ float g_P [NPTS * DD];    // pos @ pW1
__device__ float g_A [NPTS * HA];    // (q + pb2) @ aW1 + ab1   (per-i base)
__device__ float g_Bk[NPTS * HA];    // k @ aW1
__device__ float g_V [NPTS * DD];    // v
__device__ float g_C [DD * HA];      // pW2 @ aW1

// ---------------- kernel 1: per-point projections ----------------
// grid 1024 blocks (one per point), 64 threads
__global__ void pt_proj_kernel(const float* __restrict__ x,
                               const float* __restrict__ pos,
                               const float* __restrict__ Wq,
                               const float* __restrict__ Wk,
                               const float* __restrict__ Wv,
                               const float* __restrict__ pW1,
                               const float* __restrict__ pb2,
                               const float* __restrict__ aW1,
                               const float* __restrict__ ab1)
{
    __shared__ float sx[DD];
    __shared__ float sq[DD];
    __shared__ float sk[DD];
    const int i = blockIdx.x;
    const int d = threadIdx.x;

    sx[d] = x[i * DD + d];
    __syncthreads();

    float q = 0.f, k = 0.f, v = 0.f;
#pragma unroll 8
    for (int c = 0; c < DD; ++c) {
        const float xc = sx[c];
        q = fmaf(xc, Wq[c * DD + d], q);
        k = fmaf(xc, Wk[c * DD + d], k);
        v = fmaf(xc, Wv[c * DD + d], v);
    }
    const float p0 = pos[i * 2 + 0];
    const float p1 = pos[i * 2 + 1];
    const float P  = p0 * pW1[d] + p1 * pW1[DD + d];

    g_P[i * DD + d] = P;
    g_V[i * DD + d] = v;
    sq[d] = q + pb2[d];   // fold pb2@aW1 into A
    sk[d] = k;
    __syncthreads();

#pragma unroll
    for (int t = 0; t < 4; ++t) {
        const int n = t * DD + d;           // 0..255, coalesced
        float A  = ab1[n];
        float Bv = 0.f;
#pragma unroll 8
        for (int c = 0; c < DD; ++c) {
            const float w = aW1[c * HA + n];
            A  = fmaf(sq[c], w, A);
            Bv = fmaf(sk[c], w, Bv);
        }
        g_A [i * HA + n] = A;
        g_Bk[i * HA + n] = Bv;
    }
}

// ---------------- kernel 2: C = pW2 @ aW1 ----------------
// grid 64 blocks (c), 256 threads (n)
__global__ void pt_cmat_kernel(const float* __restrict__ pW2,
                               const float* __restrict__ aW1)
{
    const int c = blockIdx.x;
    const int n = threadIdx.x;
    float acc = 0.f;
#pragma unroll 8
    for (int d = 0; d < DD; ++d)
        acc = fmaf(pW2[c * DD + d], aW1[d * HA + n], acc);
    g_C[c * HA + n] = acc;
}

// ---------------- main fused kernel ----------------
// grid 1024 (one CTA per query i), 256 threads, dynamic smem
// smem layout (floats):
#define OFF_C     0
#define OFF_AW2   (OFF_C   + DD * HA)       // 16384
#define OFF_PW2   (OFF_AW2 + HA * DD)       // 16384
#define OFF_G     (OFF_PW2 + DD * DD)       //  4096
#define GSTR      68
#define OFF_H     (OFF_G   + TJ * GSTR)     //  4352
#define OFF_BASE  (OFF_H   + TJ * GSTR)     //  4352
#define OFF_PBI   (OFF_BASE + HA)           //   256
#define OFF_PB2   (OFF_PBI + DD)            //    64
#define OFF_M     (OFF_PB2 + DD)
#define OFF_L     (OFF_M   + DD)
#define OFF_ACC   (OFF_L   + DD)
#define OFF_RMAX  (OFF_ACC + DD)            //   256
#define OFF_RL    (OFF_RMAX + NT)
#define OFF_RA    (OFF_RL  + NT)
#define OFF_NEW   (OFF_RA  + NT)
#define SMEM_FLOATS (OFF_NEW + DD)

__global__ __launch_bounds__(NT, 1)
void pt_main_kernel(const float* __restrict__ pb1,
                    const float* __restrict__ pb2,
                    const float* __restrict__ pW2,
                    const float* __restrict__ aW2,
                    float* __restrict__ out)
{
    extern __shared__ float sm[];
    float* sC    = sm + OFF_C;
    float* sW2   = sm + OFF_AW2;   // aW2 [n][d]
    float* sP2   = sm + OFF_PW2;   // pW2 [c][d]
    float* sG    = sm + OFF_G;     // g / reused as S
    float* sH    = sm + OFF_H;     // h / reused as VV
    float* sBase = sm + OFF_BASE;
    float* sPbi  = sm + OFF_PBI;
    float* sPb2  = sm + OFF_PB2;
    float* sMx   = sm + OFF_M;
    float* sLs   = sm + OFF_L;
    float* sAc   = sm + OFF_ACC;
    float* sRmax = sm + OFF_RMAX;
    float* sRl   = sm + OFF_RL;
    float* sRa   = sm + OFF_RA;
    float* sNew  = sm + OFF_NEW;

    const int tid = threadIdx.x;
    const int i   = blockIdx.x;

    // --- load persistent tiles ---
    for (int idx = tid; idx < DD * HA; idx += NT) {
        sC[idx]  = g_C[idx];
        sW2[idx] = aW2[idx];
    }
    for (int idx = tid; idx < DD * DD; idx += NT) sP2[idx] = pW2[idx];
    sBase[tid] = g_A[i * HA + tid];
    if (tid < DD) {
        sPbi[tid] = g_P[i * DD + tid] + pb1[tid];
        sPb2[tid] = pb2[tid];
        sMx[tid] = -CUDART_INF_F;
        sLs[tid] = 0.f;
        sAc[tid] = 0.f;
    }
    __syncthreads();

    const int tj = tid >> 4;       // 0..15
    const int tn = tid & 15;       // 0..15
    const int r0 = tj * 4;         // row (j) base
    const int c0 = tn * 4;         // col base

    for (int jt = 0; jt < NPTS / TJ; ++jt) {
        const int jbase = jt * TJ;

        // ---- g[j][c] = relu(Pbi[c] - P[jbase+j][c]) ----
        for (int idx = tid; idx < TJ * DD; idx += NT) {
            const int j = idx >> 6;
            const int c = idx & 63;
            const float val = sPbi[c] - g_P[(jbase + j) * DD + c];
            sG[j * GSTR + c] = fmaxf(val, 0.f);
        }
        __syncthreads();

        // ---- rpe GEMM: vv = g @ pW2  (64x64, K=64) ----
        float vv[4][4];
#pragma unroll
        for (int r = 0; r < 4; ++r)
#pragma unroll
            for (int u = 0; u < 4; ++u) vv[r][u] = 0.f;

#pragma unroll 8
        for (int c = 0; c < DD; ++c) {
            const float a0 = sG[(r0 + 0) * GSTR + c];
            const float a1 = sG[(r0 + 1) * GSTR + c];
            const float a2 = sG[(r0 + 2) * GSTR + c];
            const float a3 = sG[(r0 + 3) * GSTR + c];
            const float4 b = *(const float4*)&sP2[c * DD + c0];
            vv[0][0] = fmaf(a0, b.x, vv[0][0]); vv[0][1] = fmaf(a0, b.y, vv[0][1]);
            vv[0][2] = fmaf(a0, b.z, vv[0][2]); vv[0][3] = fmaf(a0, b.w, vv[0][3]);
            vv[1][0] = fmaf(a1, b.x, vv[1][0]); vv[1][1] = fmaf(a1, b.y, vv[1][1]);
            vv[1][2] = fmaf(a1, b.z, vv[1][2]); vv[1][3] = fmaf(a1, b.w, vv[1][3]);
            vv[2][0] = fmaf(a2, b.x, vv[2][0]); vv[2][1] = fmaf(a2, b.y, vv[2][1]);
            vv[2][2] = fmaf(a2, b.z, vv[2][2]); vv[2][3] = fmaf(a2, b.w, vv[2][3]);
            vv[3][0] = fmaf(a3, b.x, vv[3][0]); vv[3][1] = fmaf(a3, b.y, vv[3][1]);
            vv[3][2] = fmaf(a3, b.z, vv[3][2]); vv[3][3] = fmaf(a3, b.w, vv[3][3]);
        }
        {
            const float4 pbv = *(const float4*)&sPb2[c0];
#pragma unroll
            for (int r = 0; r < 4; ++r) {
                const float4 vj = *(const float4*)&g_V[(jbase + r0 + r) * DD + c0];
                vv[r][0] += vj.x + pbv.x;
                vv[r][1] += vj.y + pbv.y;
                vv[r][2] += vj.z + pbv.z;
                vv[r][3] += vj.w + pbv.w;
            }
        }

        // ---- s accumulators (persist over the 4 n-passes) ----
        float sacc[4][4];
#pragma unroll
        for (int r = 0; r < 4; ++r)
#pragma unroll
            for (int u = 0; u < 4; ++u) sacc[r][u] = 0.f;

#pragma unroll 1
        for (int pass = 0; pass < 4; ++pass) {
            const int nb = pass * 64;

            // GEMM1: h = g @ C[:, nb:nb+64]   (64x64, K=64)
            float hacc[4][4];
#pragma unroll
            for (int r = 0; r < 4; ++r)
#pragma unroll
                for (int u = 0; u < 4; ++u) hacc[r][u] = 0.f;

#pragma unroll 8
            for (int c = 0; c < DD; ++c) {
                const float a0 = sG[(r0 + 0) * GSTR + c];
                const float a1 = sG[(r0 + 1) * GSTR + c];
                const float a2 = sG[(r0 + 2) * GSTR + c];
                const float a3 = sG[(r0 + 3) * GSTR + c];
                const float4 b = *(const float4*)&sC[c * HA + nb + c0];
                hacc[0][0] = fmaf(a0, b.x, hacc[0][0]); hacc[0][1] = fmaf(a0, b.y, hacc[0][1]);
                hacc[0][2] = fmaf(a0, b.z, hacc[0][2]); hacc[0][3] = fmaf(a0, b.w, hacc[0][3]);
                hacc[1][0] = fmaf(a1, b.x, hacc[1][0]); hacc[1][1] = fmaf(a1, b.y, hacc[1][1]);
                hacc[1][2] = fmaf(a1, b.z, hacc[1][2]); hacc[1][3] = fmaf(a1, b.w, hacc[1][3]);
                hacc[2][0] = fmaf(a2, b.x, hacc[2][0]); hacc[2][1] = fmaf(a2, b.y, hacc[2][1]);
                hacc[2][2] = fmaf(a2, b.z, hacc[2][2]); hacc[2][3] = fmaf(a2, b.w, hacc[2][3]);
                hacc[3][0] = fmaf(a3, b.x, hacc[3][0]); hacc[3][1] = fmaf(a3, b.y, hacc[3][1]);
                hacc[3][2] = fmaf(a3, b.z, hacc[3][2]); hacc[3][3] = fmaf(a3, b.w, hacc[3][3]);
            }

            // epilogue: + base - Bk, relu, store to sH
            {
                const float4 bs = *(const float4*)&sBase[nb + c0];
#pragma unroll
                for (int r = 0; r < 4; ++r) {
                    const float4 bk = *(const float4*)&g_Bk[(jbase + r0 + r) * HA + nb + c0];
                    float4 h;
                    h.x = fmaxf(hacc[r][0] + bs.x - bk.x, 0.f);
                    h.y = fmaxf(hacc[r][1] + bs.y - bk.y, 0.f);
                    h.z = fmaxf(hacc[r][2] + bs.z - bk.z, 0.f);
                    h.w = fmaxf(hacc[r][3] + bs.w - bk.w, 0.f);
                    *(float4*)&sH[(r0 + r) * GSTR + c0] = h;
                }
            }
            __syncthreads();

            // GEMM2 partial: sacc += relu(h) @ aW2[nb:nb+64, :]
#pragma unroll 8
            for (int nl = 0; nl < 64; ++nl) {
                const float a0 = sH[(r0 + 0) * GSTR + nl];
                const float a1 = sH[(r0 + 1) * GSTR + nl];
                const float a2 = sH[(r0 + 2) * GSTR + nl];
                const float a3 = sH[(r0 + 3) * GSTR + nl];
                const float4 b = *(const float4*)&sW2[(nb + nl) * DD + c0];
                sacc[0][0] = fmaf(a0, b.x, sacc[0][0]); sacc[0][1] = fmaf(a0, b.y, sacc[0][1]);
                sacc[0][2] = fmaf(a0, b.z, sacc[0][2]); sacc[0][3] = fmaf(a0, b.w, sacc[0][3]);
                sacc[1][0] = fmaf(a1, b.x, sacc[1][0]); sacc[1][1] = fmaf(a1, b.y, sacc[1][1]);
                sacc[1][2] = fmaf(a1, b.z, sacc[1][2]); sacc[1][3] = fmaf(a1, b.w, sacc[1][3]);
                sacc[2][0] = fmaf(a2, b.x, sacc[2][0]); sacc[2][1] = fmaf(a2, b.y, sacc[2][1]);
                sacc[2][2] = fmaf(a2, b.z, sacc[2][2]); sacc[2][3] = fmaf(a2, b.w, sacc[2][3]);
                sacc[3][0] = fmaf(a3, b.x, sacc[3][0]); sacc[3][1] = fmaf(a3, b.y, sacc[3][1]);
                sacc[3][2] = fmaf(a3, b.z, sacc[3][2]); sacc[3][3] = fmaf(a3, b.w, sacc[3][3]);
            }
            __syncthreads();   // sH reused next pass
        }

        // ---- spill s (into sG region) and vv (into sH region) ----
#pragma unroll
        for (int r = 0; r < 4; ++r) {
            float4 s4; s4.x = sacc[r][0]; s4.y = sacc[r][1]; s4.z = sacc[r][2]; s4.w = sacc[r][3];
            *(float4*)&sG[(r0 + r) * GSTR + c0] = s4;
            float4 v4; v4.x = vv[r][0]; v4.y = vv[r][1]; v4.z = vv[r][2]; v4.w = vv[r][3];
            *(float4*)&sH[(r0 + r) * GSTR + c0] = v4;
        }
        __syncthreads();

        // ---- online softmax update over this j-tile (per channel d) ----
        {
            const int d = tid & 63;
            const int p = tid >> 6;       // 0..3
            const int j0 = p * 16;

            float mloc = -CUDART_INF_F;
#pragma unroll 4
            for (int jj = j0; jj < j0 + 16; ++jj)
                mloc = fmaxf(mloc, sG[jj * GSTR + d]);
            sRmax[p * 64 + d] = mloc;
            __syncthreads();

            if (tid < DD) {
                float nm = fmaxf(fmaxf(sRmax[tid], sRmax[64 + tid]),
                                 fmaxf(sRmax[128 + tid], sRmax[192 + tid]));
                nm = fmaxf(nm, sMx[tid]);
                sNew[tid] = nm;
            }
            __syncthreads();

            const float nm = sNew[d];
            float sl = 0.f, sa = 0.f;
#pragma unroll 4
            for (int jj = j0; jj < j0 + 16; ++jj) {
                const float e = __expf(sG[jj * GSTR + d] - nm);
                sl += e;
                sa = fmaf(e, sH[jj * GSTR + d], sa);
            }
            sRl[p * 64 + d] = sl;
            sRa[p * 64 + d] = sa;
            __syncthreads();

            if (tid < DD) {
                const float f = __expf(sMx[tid] - sNew[tid]);  // 0 on first tile
                sLs[tid] = sLs[tid] * f + sRl[tid] + sRl[64 + tid] + sRl[128 + tid] + sRl[192 + tid];
                sAc[tid] = sAc[tid] * f + sRa[tid] + sRa[64 + tid] + sRa[128 + tid] + sRa[192 + tid];
                sMx[tid] = sNew[tid];
            }
            __syncthreads();   // sG/sH reused as g/h next tile
        }
    }

    if (tid < DD)
        out[i * DD + tid] = sAc[tid] / sLs[tid];
}

// ---------------- launch ----------------
extern "C" void kernel_launch(void* const* d_in, const int* in_sizes, int n_in,
                              void* d_out, int out_size)
{
    const float* x   = (const float*)d_in[0];
    const float* pos = (const float*)d_in[1];
    const float* Wq  = (const float*)d_in[2];
    const float* Wk  = (const float*)d_in[3];
    const float* Wv  = (const float*)d_in[4];
    const float* pW1 = (const float*)d_in[5];
    const float* pb1 = (const float*)d_in[6];
    const float* pW2 = (const float*)d_in[7];
    const float* pb2 = (const float*)d_in[8];
    const float* aW1 = (const float*)d_in[9];
    const float* ab1 = (const float*)d_in[10];
    const float* aW2 = (const float*)d_in[11];
    // ab2 (d_in[12]) is constant over j -> cancels in per-channel softmax; unused.
    float* out = (float*)d_out;

    const size_t smem_bytes = SMEM_FLOATS * sizeof(float);
    cudaFuncSetAttribute(pt_main_kernel,
                         cudaFuncAttributeMaxDynamicSharedMemorySize,
                         (int)smem_bytes);

    pt_proj_kernel<<<NPTS, DD>>>(x, pos, Wq, Wk, Wv, pW1, pb2, aW1, ab1);
    pt_cmat_kernel<<<DD, 256>>>(pW2, aW1);
    pt_main_kernel<<<NPTS, NT, smem_bytes>>>(pb1, pb2, pW2, aW2, out);
}

// round 5
// speedup vs baseline: 1.6751x; 1.6751x over previous
#include <cuda_runtime.h>
#include <math_constants.h>

#define NPTS 1024
#define DD   64
#define HA   256
#define TJ   128     // j-rows per tile (16 per warp x 8 warps)
#define NT   256
#define NTILES (NPTS / TJ)

// ---------------- device scratch ----------------
__device__ float g_P  [NPTS * DD];   // pos @ pW1
__device__ float g_A  [NPTS * HA];   // (q + pb2) @ aW1 + ab1
__device__ float g_Bk [NPTS * HA];   // k @ aW1
__device__ float g_V  [NPTS * DD];   // v
__device__ float g_C  [DD * HA];     // pW2 @ aW1
__device__ float g_Cpk [DD * HA];    // C packed as tf32 B-fragments
__device__ float g_W2pk[HA * DD];    // aW2 packed as tf32 B-fragments

// ---------------- helpers ----------------
__device__ __forceinline__ unsigned tf32u(float x) {
    unsigned u;
    asm("cvt.rna.tf32.f32 %0, %1;" : "=r"(u) : "f"(x));
    return u;
}
__device__ __forceinline__ float tf32f(float x) {
    return __uint_as_float(tf32u(x));
}
__device__ __forceinline__ void mma_tf32(float* d, const unsigned* a,
                                         unsigned b0, unsigned b1) {
    asm volatile(
        "mma.sync.aligned.m16n8k8.row.col.f32.tf32.tf32.f32 "
        "{%0,%1,%2,%3}, {%4,%5,%6,%7}, {%8,%9}, {%0,%1,%2,%3};"
        : "+f"(d[0]), "+f"(d[1]), "+f"(d[2]), "+f"(d[3])
        : "r"(a[0]), "r"(a[1]), "r"(a[2]), "r"(a[3]), "r"(b0), "r"(b1));
}

// ---------------- kernel 1: per-point projections (4 pts/block) ----------------
__global__ void pt_proj_kernel(const float* __restrict__ x,
                               const float* __restrict__ pos,
                               const float* __restrict__ Wq,
                               const float* __restrict__ Wk,
                               const float* __restrict__ Wv,
                               const float* __restrict__ pW1,
                               const float* __restrict__ pb2,
                               const float* __restrict__ aW1,
                               const float* __restrict__ ab1)
{
    __shared__ float sx[4][DD], sq[4][DD], sk[4][DD];
    const int tid = threadIdx.x;
    const int pt  = tid >> 6;
    const int d   = tid & 63;
    const int i   = blockIdx.x * 4 + pt;

    sx[pt][d] = x[i * DD + d];
    __syncthreads();

    float q = 0.f, k = 0.f, v = 0.f;
#pragma unroll 8
    for (int c = 0; c < DD; ++c) {
        const float xc = sx[pt][c];
        q = fmaf(xc, Wq[c * DD + d], q);
        k = fmaf(xc, Wk[c * DD + d], k);
        v = fmaf(xc, Wv[c * DD + d], v);
    }
    g_P[i * DD + d] = pos[i * 2] * pW1[d] + pos[i * 2 + 1] * pW1[DD + d];
    g_V[i * DD + d] = v;
    sq[pt][d] = q + pb2[d];
    sk[pt][d] = k;
    __syncthreads();

    const int n = tid;   // 0..255
    float A0 = ab1[n], A1 = A0, A2 = A0, A3 = A0;
    float B0 = 0.f, B1 = 0.f, B2 = 0.f, B3 = 0.f;
#pragma unroll 8
    for (int c = 0; c < DD; ++c) {
        const float w = aW1[c * HA + n];
        A0 = fmaf(sq[0][c], w, A0); B0 = fmaf(sk[0][c], w, B0);
        A1 = fmaf(sq[1][c], w, A1); B1 = fmaf(sk[1][c], w, B1);
        A2 = fmaf(sq[2][c], w, A2); B2 = fmaf(sk[2][c], w, B2);
        A3 = fmaf(sq[3][c], w, A3); B3 = fmaf(sk[3][c], w, B3);
    }
    const int ib = blockIdx.x * 4;
    g_A [(ib + 0) * HA + n] = A0;  g_Bk[(ib + 0) * HA + n] = B0;
    g_A [(ib + 1) * HA + n] = A1;  g_Bk[(ib + 1) * HA + n] = B1;
    g_A [(ib + 2) * HA + n] = A2;  g_Bk[(ib + 2) * HA + n] = B2;
    g_A [(ib + 3) * HA + n] = A3;  g_Bk[(ib + 3) * HA + n] = B3;
}

// ---------------- kernel 2: C = pW2 @ aW1 ----------------
__global__ void pt_cmat_kernel(const float* __restrict__ pW2,
                               const float* __restrict__ aW1)
{
    const int c = blockIdx.x;
    const int n = threadIdx.x;
    float acc = 0.f;
#pragma unroll 8
    for (int d = 0; d < DD; ++d)
        acc = fmaf(pW2[c * DD + d], aW1[d * HA + n], acc);
    g_C[c * HA + n] = acc;
}

// ---------------- kernel 3: pack B fragments (tf32-rounded) ----------------
// fragment value: b_r = B[k0 + lane%4 + 4r][n0 + lane/4]
__global__ void pt_pack_kernel(const float* __restrict__ aW2)
{
    const int gid = blockIdx.x * blockDim.x + threadIdx.x;
    if (gid < DD * HA) {
        // Cpk: layout [naG(32)][ka(8)][lane(32)][r(2)]; B = C[c][n], C row-major [64][256]
        const int idx  = gid;
        const int r    = idx & 1;
        const int lane = (idx >> 1) & 31;
        const int ka   = (idx >> 6) & 7;
        const int naG  = idx >> 9;
        const float v  = g_C[(8 * ka + (lane & 3) + 4 * r) * HA + 8 * naG + (lane >> 2)];
        g_Cpk[idx] = __uint_as_float(tf32u(v));
    } else {
        // W2pk: layout [kaG(32)][na(8)][lane(32)][r(2)]; B = aW2[k][n], aW2 row-major [256][64]
        const int idx  = gid - DD * HA;
        const int r    = idx & 1;
        const int lane = (idx >> 1) & 31;
        const int na   = (idx >> 6) & 7;
        const int kaG  = idx >> 9;
        const float v  = aW2[(8 * kaG + (lane & 3) + 4 * r) * DD + 8 * na + (lane >> 2)];
        g_W2pk[idx] = __uint_as_float(tf32u(v));
    }
}

// ---------------- main fused kernel ----------------
// smem layout (floats)
#define OFF_CPK  0
#define OFF_W2PK (OFF_CPK + DD * HA)          // 16384
#define OFF_G    (OFF_W2PK + HA * DD)         // 32768
#define GSTR     68
#define OFF_S    (OFF_G + TJ * GSTR)          // 41472 : sim / e / per-warp h scratch
#define OFF_BASE (OFF_S + TJ * GSTR)          // 50176
#define OFF_PBI  (OFF_BASE + HA)
#define OFF_MX   (OFF_PBI + DD)
#define OFF_LS   (OFF_MX + DD)
#define OFF_AC   (OFF_LS + DD)
#define OFF_F    (OFF_AC + DD)
#define OFF_R1   (OFF_F + DD)
#define OFF_R2   (OFF_R1 + NT)
#define OFF_R3   (OFF_R2 + NT)
#define SMEM_FLOATS (OFF_R3 + NT)
#define MSTR 66   // M buffer stride — MUST be even: rows are written as float2
                  // (round-4 fault: MSTR=65 made odd rows 4-byte-misaligned ST.64)

__global__ __launch_bounds__(NT, 1)
void pt_main_kernel(const float* __restrict__ pb1,
                    const float* __restrict__ pb2,
                    const float* __restrict__ pW2,
                    float* __restrict__ out)
{
    extern __shared__ float sm[];
    float* sCpk  = sm + OFF_CPK;
    float* sW2pk = sm + OFF_W2PK;
    float* sG    = sm + OFF_G;
    float* sS    = sm + OFF_S;
    float* sBase = sm + OFF_BASE;
    float* sPbi  = sm + OFF_PBI;
    float* sMx   = sm + OFF_MX;
    float* sLs   = sm + OFF_LS;
    float* sAc   = sm + OFF_AC;
    float* sF    = sm + OFF_F;
    float* sR1   = sm + OFF_R1;
    float* sR2   = sm + OFF_R2;
    float* sR3   = sm + OFF_R3;

    const int tid  = threadIdx.x;
    const int i    = blockIdx.x;
    const int w    = tid >> 5;
    const int lane = tid & 31;
    const int lrow = lane >> 2;    // 0..7
    const int t    = lane & 3;     // 0..3

    // persistent packed weights -> smem (coalesced float4)
    {
        const float4* c4 = (const float4*)g_Cpk;
        const float4* w4 = (const float4*)g_W2pk;
        float4* sc4 = (float4*)sCpk;
        float4* sw4 = (float4*)sW2pk;
#pragma unroll
        for (int r = 0; r < (DD * HA / 4) / NT; ++r) {
            sc4[tid + r * NT] = c4[tid + r * NT];
            sw4[tid + r * NT] = w4[tid + r * NT];
        }
    }
    sBase[tid] = g_A[i * HA + tid];
    if (tid < DD) {
        sPbi[tid] = g_P[i * DD + tid] + pb1[tid];
        sMx[tid]  = -CUDART_INF_F;
        sLs[tid]  = 0.f;
        sAc[tid]  = 0.f;
    }
    __syncthreads();

    // persistent M accumulator fragments: warp w owns rows d0..d0+16, cols c0..c0+32
    const int d0 = 16 * (w & 3);
    const int c0 = 32 * (w >> 2);
    float M[4][4];
#pragma unroll
    for (int na = 0; na < 4; ++na)
#pragma unroll
        for (int u = 0; u < 4; ++u) M[na][u] = 0.f;

    const int R0 = 16 * w;            // this warp's j-row base within tile
    float* sScr = sS + w * (16 * GSTR);  // per-warp h scratch (aliases sim rows R0..R0+16)

    for (int jt = 0; jt < NTILES; ++jt) {
        const int jb = jt * TJ;

        // ---- fill g tile (tf32-rounded): g[j][c] = relu(Pbi[c] - P[jb+j][c]) ----
#pragma unroll 4
        for (int idx = tid; idx < TJ * DD; idx += NT) {
            const int j = idx >> 6;
            const int c = idx & 63;
            const float val = fmaxf(sPbi[c] - g_P[(jb + j) * DD + c], 0.f);
            sG[j * GSTR + c] = tf32f(val);
        }
        __syncthreads();

        // ---- load A-fragments of g for this warp's 16 rows ----
        unsigned ga[8][4];
#pragma unroll
        for (int ka = 0; ka < 8; ++ka) {
            const int rA = (R0 + lrow) * GSTR;
            const int rB = (R0 + lrow + 8) * GSTR;
            ga[ka][0] = __float_as_uint(sG[rA + 8 * ka + t]);
            ga[ka][1] = __float_as_uint(sG[rB + 8 * ka + t]);
            ga[ka][2] = __float_as_uint(sG[rA + 8 * ka + t + 4]);
            ga[ka][3] = __float_as_uint(sG[rB + 8 * ka + t + 4]);
        }

        // ---- sim accumulators (16 rows x 64 d) ----
        float sim[8][4];
#pragma unroll
        for (int na = 0; na < 8; ++na)
#pragma unroll
            for (int u = 0; u < 4; ++u) sim[na][u] = 0.f;

#pragma unroll 1
        for (int pass = 0; pass < 4; ++pass) {
            const int nb = 64 * pass;

            // prefetch Bk for epilogue (hidden under GEMM1)
            float2 bkA[8], bkB[8];
#pragma unroll
            for (int na = 0; na < 8; ++na) {
                const int col = nb + 8 * na + 2 * t;
                bkA[na] = *(const float2*)&g_Bk[(jb + R0 + lrow) * HA + col];
                bkB[na] = *(const float2*)&g_Bk[(jb + R0 + lrow + 8) * HA + col];
            }

            // GEMM1: h[16x64] = g @ C[:, nb:nb+64]
            float h[8][4];
#pragma unroll
            for (int na = 0; na < 8; ++na)
#pragma unroll
                for (int u = 0; u < 4; ++u) h[na][u] = 0.f;

#pragma unroll
            for (int ka = 0; ka < 8; ++ka) {
#pragma unroll
                for (int na = 0; na < 8; ++na) {
                    const float2 b = *(const float2*)
                        &sCpk[(((pass * 8 + na) * 8 + ka) * 32 + lane) * 2];
                    mma_tf32(h[na], ga[ka],
                             __float_as_uint(b.x), __float_as_uint(b.y));
                }
            }

            // epilogue: + Base - Bk, relu, tf32-round, -> per-warp scratch
#pragma unroll
            for (int na = 0; na < 8; ++na) {
                const int col = nb + 8 * na + 2 * t;
                const float2 bs = *(const float2*)&sBase[col];
                float2 hA, hB;
                hA.x = tf32f(fmaxf(h[na][0] + bs.x - bkA[na].x, 0.f));
                hA.y = tf32f(fmaxf(h[na][1] + bs.y - bkA[na].y, 0.f));
                hB.x = tf32f(fmaxf(h[na][2] + bs.x - bkB[na].x, 0.f));
                hB.y = tf32f(fmaxf(h[na][3] + bs.y - bkB[na].y, 0.f));
                *(float2*)&sScr[lrow * GSTR + 8 * na + 2 * t]       = hA;
                *(float2*)&sScr[(lrow + 8) * GSTR + 8 * na + 2 * t] = hB;
            }
            __syncwarp();

            // GEMM2: sim += relu(h) @ aW2[nb:nb+64, :]
#pragma unroll
            for (int q = 0; q < 8; ++q) {
                unsigned a[4];
                a[0] = __float_as_uint(sScr[lrow * GSTR + 8 * q + t]);
                a[1] = __float_as_uint(sScr[(lrow + 8) * GSTR + 8 * q + t]);
                a[2] = __float_as_uint(sScr[lrow * GSTR + 8 * q + t + 4]);
                a[3] = __float_as_uint(sScr[(lrow + 8) * GSTR + 8 * q + t + 4]);
#pragma unroll
                for (int na = 0; na < 8; ++na) {
                    const float2 b = *(const float2*)
                        &sW2pk[(((pass * 8 + q) * 8 + na) * 32 + lane) * 2];
                    mma_tf32(sim[na], a,
                             __float_as_uint(b.x), __float_as_uint(b.y));
                }
            }
            __syncwarp();   // scratch reused next pass
        }

        // ---- write sim fragments into sS (warp's own rows) ----
#pragma unroll
        for (int na = 0; na < 8; ++na) {
            *(float2*)&sS[(R0 + lrow) * GSTR + 8 * na + 2 * t] =
                make_float2(sim[na][0], sim[na][1]);
            *(float2*)&sS[(R0 + lrow + 8) * GSTR + 8 * na + 2 * t] =
                make_float2(sim[na][2], sim[na][3]);
        }
        __syncthreads();

        // ---- online softmax over this tile (per channel d) ----
        {
            const int d  = tid & 63;
            const int p  = tid >> 6;
            const int j0 = 32 * p;

            float mloc = -CUDART_INF_F;
#pragma unroll 8
            for (int j = j0; j < j0 + 32; ++j)
                mloc = fmaxf(mloc, sS[j * GSTR + d]);
            sR1[p * 64 + d] = mloc;
            __syncthreads();

            if (tid < DD) {
                float nm = fmaxf(fmaxf(sR1[tid], sR1[64 + tid]),
                                 fmaxf(sR1[128 + tid], sR1[192 + tid]));
                nm = fmaxf(nm, sMx[tid]);
                const float f = __expf(sMx[tid] - nm);
                sMx[tid] = nm;
                sF[tid]  = f;
                sLs[tid] *= f;
                sAc[tid] *= f;
            }
            __syncthreads();

            const float nm = sMx[d];
            float sl = 0.f, sa = 0.f;
#pragma unroll 4
            for (int j = j0; j < j0 + 32; ++j) {
                const float e = __expf(sS[j * GSTR + d] - nm);
                sl += e;
                sa = fmaf(e, g_V[(jb + j) * DD + d], sa);
                sS[j * GSTR + d] = tf32f(e);
            }
            sR2[p * 64 + d] = sl;
            sR3[p * 64 + d] = sa;
            __syncthreads();

            if (tid < DD) {
                sLs[tid] += sR2[tid] + sR2[64 + tid] + sR2[128 + tid] + sR2[192 + tid];
                sAc[tid] += sR3[tid] + sR3[64 + tid] + sR3[128 + tid] + sR3[192 + tid];
            }
            __syncthreads();
        }

        // ---- M-GEMM: M[d][c] = M*f(row) + e^T @ g   (k = 128 tile rows) ----
        {
            const float fA = sF[d0 + lrow];
            const float fB = sF[d0 + lrow + 8];
#pragma unroll
            for (int na = 0; na < 4; ++na) {
                M[na][0] *= fA; M[na][1] *= fA;
                M[na][2] *= fB; M[na][3] *= fB;
            }
#pragma unroll
            for (int kk = 0; kk < 16; ++kk) {
                const int k0 = 8 * kk;
                unsigned a[4];
                a[0] = __float_as_uint(sS[(k0 + t) * GSTR + d0 + lrow]);
                a[1] = __float_as_uint(sS[(k0 + t) * GSTR + d0 + lrow + 8]);
                a[2] = __float_as_uint(sS[(k0 + t + 4) * GSTR + d0 + lrow]);
                a[3] = __float_as_uint(sS[(k0 + t + 4) * GSTR + d0 + lrow + 8]);
#pragma unroll
                for (int na = 0; na < 4; ++na) {
                    const unsigned b0 = __float_as_uint(sG[(k0 + t) * GSTR + c0 + 8 * na + lrow]);
                    const unsigned b1 = __float_as_uint(sG[(k0 + t + 4) * GSTR + c0 + 8 * na + lrow]);
                    mma_tf32(M[na], a, b0, b1);
                }
            }
        }
        __syncthreads();   // sG / sS reused next tile
    }

    // ---- final: rpe_d = sum_c M[d][c] * pW2[c][d]; out = (acc + Ls*pb2 + rpe)/Ls ----
#pragma unroll
    for (int na = 0; na < 4; ++na) {
        *(float2*)&sG[(d0 + lrow) * MSTR + c0 + 8 * na + 2 * t] =
            make_float2(M[na][0], M[na][1]);
        *(float2*)&sG[(d0 + lrow + 8) * MSTR + c0 + 8 * na + 2 * t] =
            make_float2(M[na][2], M[na][3]);
    }
    __syncthreads();
    {
        const int d = tid & 63;
        const int q = tid >> 6;
        float part = 0.f;
#pragma unroll 4
        for (int c = 16 * q; c < 16 * q + 16; ++c)
            part = fmaf(sG[d * MSTR + c], pW2[c * DD + d], part);
        sR1[q * 64 + d] = part;
    }
    __syncthreads();
    if (tid < DD) {
        const float rpe = sR1[tid] + sR1[64 + tid] + sR1[128 + tid] + sR1[192 + tid];
        out[i * DD + tid] = (sAc[tid] + sLs[tid] * pb2[tid] + rpe) / sLs[tid];
    }
}

// ---------------- launch ----------------
extern "C" void kernel_launch(void* const* d_in, const int* in_sizes, int n_in,
                              void* d_out, int out_size)
{
    const float* x   = (const float*)d_in[0];
    const float* pos = (const float*)d_in[1];
    const float* Wq  = (const float*)d_in[2];
    const float* Wk  = (const float*)d_in[3];
    const float* Wv  = (const float*)d_in[4];
    const float* pW1 = (const float*)d_in[5];
    const float* pb1 = (const float*)d_in[6];
    const float* pW2 = (const float*)d_in[7];
    const float* pb2 = (const float*)d_in[8];
    const float* aW1 = (const float*)d_in[9];
    const float* ab1 = (const float*)d_in[10];
    const float* aW2 = (const float*)d_in[11];
    // ab2 constant over j -> cancels in per-channel softmax
    float* out = (float*)d_out;

    const size_t smem_bytes = SMEM_FLOATS * sizeof(float);
    cudaFuncSetAttribute(pt_main_kernel,
                         cudaFuncAttributeMaxDynamicSharedMemorySize,
                         (int)smem_bytes);

    pt_proj_kernel<<<NPTS / 4, NT>>>(x, pos, Wq, Wk, Wv, pW1, pb2, aW1, ab1);
    pt_cmat_kernel<<<DD, HA>>>(pW2, aW1);
    pt_pack_kernel<<<(2 * DD * HA) / NT, NT>>>(aW2);
    pt_main_kernel<<<NPTS, NT, smem_bytes>>>(pb1, pb2, pW2, out);
}

// round 8
// speedup vs baseline: 4.5403x; 2.7105x over previous
#include <cuda_runtime.h>
#include <math_constants.h>

#define NPTS 1024
#define DD   64
#define HA   256
#define TJ   128     // j-rows per tile (16 per warp x 8 warps)
#define NT   256
#define NTILES (NPTS / TJ)

// ---------------- device scratch ----------------
__device__ float g_P [NPTS * DD];    // pos @ pW1
__device__ float g_A [NPTS * HA];    // (q + pb2) @ aW1 + ab1
__device__ float g_Bk[NPTS * HA];    // k @ aW1
__device__ float g_V [NPTS * DD];    // v
__device__ float g_C [DD * HA];      // pW2 @ aW1
__device__ uint2 g_Cpk16 [4096];     // C packed as fp16 B-fragments  (4 pass x 8 na x 4 ka x 32 lane)
__device__ uint2 g_W2pk16[4096];     // aW2 packed fp16 B-fragments
__device__ uint2 g_Ppk16 [1024];     // pW2 packed fp16 B-fragments   (8 na x 4 ka x 32 lane)

// ---------------- helpers ----------------
// pack two f32 -> f16x2 (lo -> lower half, hi -> upper half)
__device__ __forceinline__ unsigned h2(float lo, float hi) {
    unsigned r;
    asm("cvt.rn.f16x2.f32 %0, %1, %2;" : "=r"(r) : "f"(hi), "f"(lo));  // first src -> upper half
    return r;
}
__device__ __forceinline__ void mma_f16(float* d, const unsigned* a,
                                        unsigned b0, unsigned b1) {
    asm volatile(
        "mma.sync.aligned.m16n8k16.row.col.f32.f16.f16.f32 "
        "{%0,%1,%2,%3}, {%4,%5,%6,%7}, {%8,%9}, {%0,%1,%2,%3};"
        : "+f"(d[0]), "+f"(d[1]), "+f"(d[2]), "+f"(d[3])
        : "r"(a[0]), "r"(a[1]), "r"(a[2]), "r"(a[3]), "r"(b0), "r"(b1));
}

// ---------------- kernel 1: per-point projections (4 pts/block) ----------------
__global__ void pt_proj_kernel(const float* __restrict__ x,
                               const float* __restrict__ pos,
                               const float* __restrict__ Wq,
                               const float* __restrict__ Wk,
                               const float* __restrict__ Wv,
                               const float* __restrict__ pW1,
                               const float* __restrict__ pb2,
                               const float* __restrict__ aW1,
                               const float* __restrict__ ab1)
{
    __shared__ float sx[4][DD], sq[4][DD], sk[4][DD];
    const int tid = threadIdx.x;
    const int pt  = tid >> 6;
    const int d   = tid & 63;
    const int i   = blockIdx.x * 4 + pt;

    sx[pt][d] = x[i * DD + d];
    __syncthreads();

    float q = 0.f, k = 0.f, v = 0.f;
#pragma unroll 8
    for (int c = 0; c < DD; ++c) {
        const float xc = sx[pt][c];
        q = fmaf(xc, Wq[c * DD + d], q);
        k = fmaf(xc, Wk[c * DD + d], k);
        v = fmaf(xc, Wv[c * DD + d], v);
    }
    g_P[i * DD + d] = pos[i * 2] * pW1[d] + pos[i * 2 + 1] * pW1[DD + d];
    g_V[i * DD + d] = v;
    sq[pt][d] = q + pb2[d];
    sk[pt][d] = k;
    __syncthreads();

    const int n = tid;
    float A0 = ab1[n], A1 = A0, A2 = A0, A3 = A0;
    float B0 = 0.f, B1 = 0.f, B2 = 0.f, B3 = 0.f;
#pragma unroll 8
    for (int c = 0; c < DD; ++c) {
        const float w = aW1[c * HA + n];
        A0 = fmaf(sq[0][c], w, A0); B0 = fmaf(sk[0][c], w, B0);
        A1 = fmaf(sq[1][c], w, A1); B1 = fmaf(sk[1][c], w, B1);
        A2 = fmaf(sq[2][c], w, A2); B2 = fmaf(sk[2][c], w, B2);
        A3 = fmaf(sq[3][c], w, A3); B3 = fmaf(sk[3][c], w, B3);
    }
    const int ib = blockIdx.x * 4;
    g_A [(ib + 0) * HA + n] = A0;  g_Bk[(ib + 0) * HA + n] = B0;
    g_A [(ib + 1) * HA + n] = A1;  g_Bk[(ib + 1) * HA + n] = B1;
    g_A [(ib + 2) * HA + n] = A2;  g_Bk[(ib + 2) * HA + n] = B2;
    g_A [(ib + 3) * HA + n] = A3;  g_Bk[(ib + 3) * HA + n] = B3;
}

// ---------------- kernel 2: C = pW2 @ aW1 ----------------
__global__ void pt_cmat_kernel(const float* __restrict__ pW2,
                               const float* __restrict__ aW1)
{
    const int c = blockIdx.x;
    const int n = threadIdx.x;
    float acc = 0.f;
#pragma unroll 8
    for (int d = 0; d < DD; ++d)
        acc = fmaf(pW2[c * DD + d], aW1[d * HA + n], acc);
    g_C[c * HA + n] = acc;
}

// ---------------- kernel 3: pack fp16 B-fragments ----------------
// m16n8k16 B layout: b0 = {B[k0+2t][n], B[k0+2t+1][n]}, b1 = {B[k0+2t+8][n], B[k0+2t+9][n]}
__global__ void pt_pack16_kernel(const float* __restrict__ aW2,
                                 const float* __restrict__ pW2)
{
    const int gid = blockIdx.x * blockDim.x + threadIdx.x;
    if (gid < 4096) {
        // Cpk16: B = C [64 c][256 n], index ((pass*8+na)*4+ka)*32+lane
        const int lane = gid & 31, ka = (gid >> 5) & 3, na = (gid >> 7) & 7, pass = gid >> 10;
        const int n  = 64 * pass + 8 * na + (lane >> 2);
        const int k0 = 16 * ka + 2 * (lane & 3);
        g_Cpk16[gid] = make_uint2(
            h2(g_C[(k0)     * HA + n], g_C[(k0 + 1) * HA + n]),
            h2(g_C[(k0 + 8) * HA + n], g_C[(k0 + 9) * HA + n]));
    } else if (gid < 8192) {
        // W2pk16: B = aW2 [256 k][64 d], index ((pass*8+na)*4+qa)*32+lane
        const int idx = gid - 4096;
        const int lane = idx & 31, qa = (idx >> 5) & 3, na = (idx >> 7) & 7, pass = idx >> 10;
        const int d  = 8 * na + (lane >> 2);
        const int k0 = 64 * pass + 16 * qa + 2 * (lane & 3);
        g_W2pk16[idx] = make_uint2(
            h2(aW2[(k0)     * DD + d], aW2[(k0 + 1) * DD + d]),
            h2(aW2[(k0 + 8) * DD + d], aW2[(k0 + 9) * DD + d]));
    } else if (gid < 9216) {
        // Ppk16: B = pW2 [64 c][64 d], index (na*4+ka)*32+lane
        const int idx = gid - 8192;
        const int lane = idx & 31, ka = (idx >> 5) & 3, na = idx >> 7;
        const int d  = 8 * na + (lane >> 2);
        const int k0 = 16 * ka + 2 * (lane & 3);
        g_Ppk16[idx] = make_uint2(
            h2(pW2[(k0)     * DD + d], pW2[(k0 + 1) * DD + d]),
            h2(pW2[(k0 + 8) * DD + d], pW2[(k0 + 9) * DD + d]));
    }
}

// ---------------- main fused kernel ----------------
// smem byte offsets
#define OFFB_CPK   0          // 32768  uint2 Cpk16
#define OFFB_W2PK  32768      // 32768  uint2 W2pk16
#define OFFB_PPK   65536      // 8192   uint2 Ppk16
#define OFFB_G     73728      // 18432  fp16 g tile [128][72] (u32 stride 36)
#define OFFB_SCR   92160      // 18432  per-warp h scratch (16 x 72 fp16 each)
#define OFFB_BASE  110592     // 1024   f32 Base[256]
#define OFFB_PBI   111616     // 256    f32 Pbi[64]
#define OFFB_MX    111872     // 256    f32 running max
#define OFFB_F     112128     // 256    f32 rescale factor
#define OFFB_R1    112384     // 2048   8 warps x 64 staging
#define OFFB_R2    114432     // 2048
#define SMEM_BYTES 116480

__global__ __launch_bounds__(NT, 1)
void pt_main_kernel(const float* __restrict__ pb1,
                    const float* __restrict__ pb2,
                    float* __restrict__ out)
{
    extern __shared__ __align__(16) unsigned char smx[];
    uint2*    sCpk  = (uint2*)(smx + OFFB_CPK);
    uint2*    sW2pk = (uint2*)(smx + OFFB_W2PK);
    uint2*    sPpk  = (uint2*)(smx + OFFB_PPK);
    unsigned* sG    = (unsigned*)(smx + OFFB_G);     // u32 view of f16x2, 36 u32/row
    unsigned* sScrB = (unsigned*)(smx + OFFB_SCR);
    float*    sBase = (float*)(smx + OFFB_BASE);
    float*    sPbi  = (float*)(smx + OFFB_PBI);
    float*    sMx   = (float*)(smx + OFFB_MX);
    float*    sF    = (float*)(smx + OFFB_F);
    float*    sR1   = (float*)(smx + OFFB_R1);
    float*    sR2   = (float*)(smx + OFFB_R2);

    const int tid  = threadIdx.x;
    const int i    = blockIdx.x;
    const int w    = tid >> 5;
    const int lane = tid & 31;
    const int lrow = lane >> 2;     // 0..7
    const int t4   = lane & 3;      // 0..3
    const int R0   = 16 * w;        // warp's j-row base within tile
    unsigned* sScr = sScrB + w * 576;   // 16 rows x 36 u32

    // ---- load persistent packed weights + per-i state ----
    {
        const uint4* c4 = (const uint4*)g_Cpk16;
        const uint4* w4 = (const uint4*)g_W2pk16;
        const uint4* p4 = (const uint4*)g_Ppk16;
        uint4* sc = (uint4*)sCpk;
        uint4* sw = (uint4*)sW2pk;
        uint4* sp = (uint4*)sPpk;
#pragma unroll
        for (int r = 0; r < 8; ++r) {
            sc[tid + r * NT] = c4[tid + r * NT];
            sw[tid + r * NT] = w4[tid + r * NT];
        }
#pragma unroll
        for (int r = 0; r < 2; ++r) sp[tid + r * NT] = p4[tid + r * NT];
    }
    sBase[tid] = g_A[i * HA + tid];
    if (tid < DD) {
        sPbi[tid] = g_P[i * DD + tid] + pb1[tid];
        sMx[tid]  = -CUDART_INF_F;
    }
    __syncthreads();

    // per-thread channel-slot accumulators: slot (na,u) -> channel 8na+2t4+u
    float lacc[8][2], pacc[8][2];
#pragma unroll
    for (int na = 0; na < 8; ++na) {
        lacc[na][0] = lacc[na][1] = 0.f;
        pacc[na][0] = pacc[na][1] = 0.f;
    }

    for (int jt = 0; jt < NTILES; ++jt) {
        const int jb = jt * TJ;

        // ---- fill g tile fp16: g[j][c] = relu(Pbi[c] - P[jb+j][c]) ----
#pragma unroll 4
        for (int idx = tid; idx < TJ * 32; idx += NT) {
            const int row = idx >> 5, cp = idx & 31;
            const float2 pv = *(const float2*)&g_P[(jb + row) * DD + 2 * cp];
            const float2 pb = *(const float2*)&sPbi[2 * cp];
            sG[row * 36 + cp] = h2(fmaxf(pb.x - pv.x, 0.f), fmaxf(pb.y - pv.y, 0.f));
        }
        __syncthreads();

        // ---- A-fragments of g (k=64 -> 4 ka groups) ----
        unsigned ga[4][4];
#pragma unroll
        for (int ka = 0; ka < 4; ++ka) {
            const int rA = (R0 + lrow) * 36, rB = (R0 + lrow + 8) * 36;
            ga[ka][0] = sG[rA + 8 * ka + t4];
            ga[ka][1] = sG[rB + 8 * ka + t4];
            ga[ka][2] = sG[rA + 8 * ka + t4 + 4];
            ga[ka][3] = sG[rB + 8 * ka + t4 + 4];
        }

        // ---- prefetch v fragments for this tile ----
        float2 vA[8], vB[8];
#pragma unroll
        for (int na = 0; na < 8; ++na) {
            const int col = 8 * na + 2 * t4;
            vA[na] = *(const float2*)&g_V[(jb + R0 + lrow)     * DD + col];
            vB[na] = *(const float2*)&g_V[(jb + R0 + lrow + 8) * DD + col];
        }

        float sim[8][4];
#pragma unroll
        for (int na = 0; na < 8; ++na)
#pragma unroll
            for (int u = 0; u < 4; ++u) sim[na][u] = 0.f;

#pragma unroll 1
        for (int pass = 0; pass < 4; ++pass) {
            // prefetch Bk (hidden under GEMM1)
            float2 bkA[8], bkB[8];
#pragma unroll
            for (int na = 0; na < 8; ++na) {
                const int col = 64 * pass + 8 * na + 2 * t4;
                bkA[na] = *(const float2*)&g_Bk[(jb + R0 + lrow)     * HA + col];
                bkB[na] = *(const float2*)&g_Bk[(jb + R0 + lrow + 8) * HA + col];
            }

            // GEMM1: h[16x64] = g @ C[:, pass*64 : +64]
            float h[8][4];
#pragma unroll
            for (int na = 0; na < 8; ++na)
#pragma unroll
                for (int u = 0; u < 4; ++u) h[na][u] = 0.f;
#pragma unroll
            for (int ka = 0; ka < 4; ++ka)
#pragma unroll
                for (int na = 0; na < 8; ++na) {
                    const uint2 b = sCpk[((pass * 8 + na) * 4 + ka) * 32 + lane];
                    mma_f16(h[na], ga[ka], b.x, b.y);
                }

            // epilogue: + Base - Bk, relu, -> fp16 scratch
#pragma unroll
            for (int na = 0; na < 8; ++na) {
                const int col = 64 * pass + 8 * na + 2 * t4;
                const float2 bs = *(const float2*)&sBase[col];
                sScr[lrow * 36 + 4 * na + t4] =
                    h2(fmaxf(h[na][0] + bs.x - bkA[na].x, 0.f),
                       fmaxf(h[na][1] + bs.y - bkA[na].y, 0.f));
                sScr[(lrow + 8) * 36 + 4 * na + t4] =
                    h2(fmaxf(h[na][2] + bs.x - bkB[na].x, 0.f),
                       fmaxf(h[na][3] + bs.y - bkB[na].y, 0.f));
            }
            __syncwarp();

            // GEMM2: sim += relu(h) @ aW2[pass*64 : +64, :]
#pragma unroll
            for (int qa = 0; qa < 4; ++qa) {
                unsigned a2[4];
                a2[0] = sScr[lrow * 36 + 8 * qa + t4];
                a2[1] = sScr[(lrow + 8) * 36 + 8 * qa + t4];
                a2[2] = sScr[lrow * 36 + 8 * qa + t4 + 4];
                a2[3] = sScr[(lrow + 8) * 36 + 8 * qa + t4 + 4];
#pragma unroll
                for (int na = 0; na < 8; ++na) {
                    const uint2 b = sW2pk[((pass * 8 + na) * 4 + qa) * 32 + lane];
                    mma_f16(sim[na], a2, b.x, b.y);
                }
            }
            __syncwarp();
        }

        // ---- rpe GEMM: rp[16x64] = g @ pW2 (fragment layout == sim layout) ----
        float rp[8][4];
#pragma unroll
        for (int na = 0; na < 8; ++na)
#pragma unroll
            for (int u = 0; u < 4; ++u) rp[na][u] = 0.f;
#pragma unroll
        for (int ka = 0; ka < 4; ++ka)
#pragma unroll
            for (int na = 0; na < 8; ++na) {
                const uint2 b = sPpk[(na * 4 + ka) * 32 + lane];
                mma_f16(rp[na], ga[ka], b.x, b.y);
            }

        // ---- softmax (register-resident): per-slot max -> shfl -> cross-warp ----
        float mx[8][2];
#pragma unroll
        for (int na = 0; na < 8; ++na) {
            mx[na][0] = fmaxf(sim[na][0], sim[na][2]);
            mx[na][1] = fmaxf(sim[na][1], sim[na][3]);
        }
#pragma unroll
        for (int off = 4; off < 32; off <<= 1)
#pragma unroll
            for (int na = 0; na < 8; ++na) {
                mx[na][0] = fmaxf(mx[na][0], __shfl_xor_sync(0xffffffffu, mx[na][0], off));
                mx[na][1] = fmaxf(mx[na][1], __shfl_xor_sync(0xffffffffu, mx[na][1], off));
            }
        if (lane < 4) {
#pragma unroll
            for (int na = 0; na < 8; ++na) {
                sR1[w * 64 + 8 * na + 2 * lane]     = mx[na][0];
                sR1[w * 64 + 8 * na + 2 * lane + 1] = mx[na][1];
            }
        }
        __syncthreads();

        if (tid < DD) {
            float gm = sR1[tid];
#pragma unroll
            for (int ww = 1; ww < 8; ++ww) gm = fmaxf(gm, sR1[ww * 64 + tid]);
            const float nm = fmaxf(gm, sMx[tid]);
            sF[tid]  = __expf(sMx[tid] - nm);
            sMx[tid] = nm;
        }
        __syncthreads();

        // ---- e + accumulate (registers) ----
#pragma unroll
        for (int na = 0; na < 8; ++na) {
            const int ch = 8 * na + 2 * t4;
            const float2 nm2 = *(const float2*)&sMx[ch];
            const float2 f2v = *(const float2*)&sF[ch];
            const float e00 = __expf(sim[na][0] - nm2.x);
            const float e10 = __expf(sim[na][2] - nm2.x);
            const float e01 = __expf(sim[na][1] - nm2.y);
            const float e11 = __expf(sim[na][3] - nm2.y);
            lacc[na][0] = lacc[na][0] * f2v.x + e00 + e10;
            lacc[na][1] = lacc[na][1] * f2v.y + e01 + e11;
            pacc[na][0] = pacc[na][0] * f2v.x
                        + e00 * (vA[na].x + rp[na][0]) + e10 * (vB[na].x + rp[na][2]);
            pacc[na][1] = pacc[na][1] * f2v.y
                        + e01 * (vA[na].y + rp[na][1]) + e11 * (vB[na].y + rp[na][3]);
        }
        // next iteration's g-fill + its __syncthreads provide the hazard fence
    }

    // ---- final reduction: over lrow (shfl), then over warps (smem) ----
#pragma unroll
    for (int off = 4; off < 32; off <<= 1)
#pragma unroll
        for (int na = 0; na < 8; ++na) {
            lacc[na][0] += __shfl_xor_sync(0xffffffffu, lacc[na][0], off);
            lacc[na][1] += __shfl_xor_sync(0xffffffffu, lacc[na][1], off);
            pacc[na][0] += __shfl_xor_sync(0xffffffffu, pacc[na][0], off);
            pacc[na][1] += __shfl_xor_sync(0xffffffffu, pacc[na][1], off);
        }
    __syncthreads();   // sR1 free (previous tile consumers done)
    if (lane < 4) {
#pragma unroll
        for (int na = 0; na < 8; ++na) {
            sR1[w * 64 + 8 * na + 2 * lane]     = lacc[na][0];
            sR1[w * 64 + 8 * na + 2 * lane + 1] = lacc[na][1];
            sR2[w * 64 + 8 * na + 2 * lane]     = pacc[na][0];
            sR2[w * 64 + 8 * na + 2 * lane + 1] = pacc[na][1];
        }
    }
    __syncthreads();
    if (tid < DD) {
        float L = 0.f, P = 0.f;
#pragma unroll
        for (int ww = 0; ww < 8; ++ww) {
            L += sR1[ww * 64 + tid];
            P += sR2[ww * 64 + tid];
        }
        out[i * DD + tid] = (P + L * pb2[tid]) / L;
    }
}

// ---------------- launch ----------------
extern "C" void kernel_launch(void* const* d_in, const int* in_sizes, int n_in,
                              void* d_out, int out_size)
{
    const float* x   = (const float*)d_in[0];
    const float* pos = (const float*)d_in[1];
    const float* Wq  = (const float*)d_in[2];
    const float* Wk  = (const float*)d_in[3];
    const float* Wv  = (const float*)d_in[4];
    const float* pW1 = (const float*)d_in[5];
    const float* pb1 = (const float*)d_in[6];
    const float* pW2 = (const float*)d_in[7];
    const float* pb2 = (const float*)d_in[8];
    const float* aW1 = (const float*)d_in[9];
    const float* ab1 = (const float*)d_in[10];
    const float* aW2 = (const float*)d_in[11];
    // ab2 constant over j -> cancels in per-channel softmax
    float* out = (float*)d_out;

    cudaFuncSetAttribute(pt_main_kernel,
                         cudaFuncAttributeMaxDynamicSharedMemorySize,
                         SMEM_BYTES);

    pt_proj_kernel<<<NPTS / 4, NT>>>(x, pos, Wq, Wk, Wv, pW1, pb2, aW1, ab1);
    pt_cmat_kernel<<<DD, HA>>>(pW2, aW1);
    pt_pack16_kernel<<<36, NT>>>(aW2, pW2);
    pt_main_kernel<<<NPTS, NT, SMEM_BYTES>>>(pb1, pb2, out);
}

// round 10
// speedup vs baseline: 5.4161x; 1.1929x over previous
#include <cuda_runtime.h>
#include <math_constants.h>

#define NPTS 1024
#define DD   64
#define HA   256
#define TJ   256     // j-rows per tile (32 per warp x 8 warps)
#define NT   256
#define NTILES (NPTS / TJ)

// ---------------- device scratch ----------------
__device__ float g_P [NPTS * DD];    // pos @ pW1
__device__ float g_A [NPTS * HA];    // (q + pb2) @ aW1 + ab1
__device__ float g_Bk[NPTS * HA];    // k @ aW1
__device__ float g_V [NPTS * DD];    // v
__device__ float g_C [DD * HA];      // pW2 @ aW1
__device__ uint2 g_Cpk16 [4096];     // C packed as fp16 B-fragments  (4 pass x 8 na x 4 ka x 32 lane)
__device__ uint2 g_W2pk16[4096];     // aW2 packed fp16 B-fragments
__device__ uint2 g_Ppk16 [1024];     // pW2 packed fp16 B-fragments   (8 na x 4 ka x 32 lane)

// ---------------- helpers ----------------
// pack two f32 -> f16x2 (lo -> lower half, hi -> upper half)
__device__ __forceinline__ unsigned h2(float lo, float hi) {
    unsigned r;
    asm("cvt.rn.f16x2.f32 %0, %1, %2;" : "=r"(r) : "f"(hi), "f"(lo));  // first src -> upper half
    return r;
}
__device__ __forceinline__ void mma_f16(float* d, const unsigned* a,
                                        unsigned b0, unsigned b1) {
    asm volatile(
        "mma.sync.aligned.m16n8k16.row.col.f32.f16.f16.f32 "
        "{%0,%1,%2,%3}, {%4,%5,%6,%7}, {%8,%9}, {%0,%1,%2,%3};"
        : "+f"(d[0]), "+f"(d[1]), "+f"(d[2]), "+f"(d[3])
        : "r"(a[0]), "r"(a[1]), "r"(a[2]), "r"(a[3]), "r"(b0), "r"(b1));
}

// ---------------- kernel 1: per-point projections (4 pts/block) ----------------
__global__ void pt_proj_kernel(const float* __restrict__ x,
                               const float* __restrict__ pos,
                               const float* __restrict__ Wq,
                               const float* __restrict__ Wk,
                               const float* __restrict__ Wv,
                               const float* __restrict__ pW1,
                               const float* __restrict__ pb2,
                               const float* __restrict__ aW1,
                               const float* __restrict__ ab1)
{
    __shared__ float sx[4][DD], sq[4][DD], sk[4][DD];
    const int tid = threadIdx.x;
    const int pt  = tid >> 6;
    const int d   = tid & 63;
    const int i   = blockIdx.x * 4 + pt;

    sx[pt][d] = x[i * DD + d];
    __syncthreads();

    float q = 0.f, k = 0.f, v = 0.f;
#pragma unroll 8
    for (int c = 0; c < DD; ++c) {
        const float xc = sx[pt][c];
        q = fmaf(xc, Wq[c * DD + d], q);
        k = fmaf(xc, Wk[c * DD + d], k);
        v = fmaf(xc, Wv[c * DD + d], v);
    }
    g_P[i * DD + d] = pos[i * 2] * pW1[d] + pos[i * 2 + 1] * pW1[DD + d];
    g_V[i * DD + d] = v;
    sq[pt][d] = q + pb2[d];
    sk[pt][d] = k;
    __syncthreads();

    const int n = tid;
    float A0 = ab1[n], A1 = A0, A2 = A0, A3 = A0;
    float B0 = 0.f, B1 = 0.f, B2 = 0.f, B3 = 0.f;
#pragma unroll 8
    for (int c = 0; c < DD; ++c) {
        const float w = aW1[c * HA + n];
        A0 = fmaf(sq[0][c], w, A0); B0 = fmaf(sk[0][c], w, B0);
        A1 = fmaf(sq[1][c], w, A1); B1 = fmaf(sk[1][c], w, B1);
        A2 = fmaf(sq[2][c], w, A2); B2 = fmaf(sk[2][c], w, B2);
        A3 = fmaf(sq[3][c], w, A3); B3 = fmaf(sk[3][c], w, B3);
    }
    const int ib = blockIdx.x * 4;
    g_A [(ib + 0) * HA + n] = A0;  g_Bk[(ib + 0) * HA + n] = B0;
    g_A [(ib + 1) * HA + n] = A1;  g_Bk[(ib + 1) * HA + n] = B1;
    g_A [(ib + 2) * HA + n] = A2;  g_Bk[(ib + 2) * HA + n] = B2;
    g_A [(ib + 3) * HA + n] = A3;  g_Bk[(ib + 3) * HA + n] = B3;
}

// ---------------- kernel 2: C = pW2 @ aW1 ----------------
__global__ void pt_cmat_kernel(const float* __restrict__ pW2,
                               const float* __restrict__ aW1)
{
    const int c = blockIdx.x;
    const int n = threadIdx.x;
    float acc = 0.f;
#pragma unroll 8
    for (int d = 0; d < DD; ++d)
        acc = fmaf(pW2[c * DD + d], aW1[d * HA + n], acc);
    g_C[c * HA + n] = acc;
}

// ---------------- kernel 3: pack fp16 B-fragments ----------------
// m16n8k16 B layout: b0 = {B[k0+2t][n], B[k0+2t+1][n]}, b1 = {B[k0+2t+8][n], B[k0+2t+9][n]}
__global__ void pt_pack16_kernel(const float* __restrict__ aW2,
                                 const float* __restrict__ pW2)
{
    const int gid = blockIdx.x * blockDim.x + threadIdx.x;
    if (gid < 4096) {
        // Cpk16: B = C [64 c][256 n], index ((pass*8+na)*4+ka)*32+lane
        const int lane = gid & 31, ka = (gid >> 5) & 3, na = (gid >> 7) & 7, pass = gid >> 10;
        const int n  = 64 * pass + 8 * na + (lane >> 2);
        const int k0 = 16 * ka + 2 * (lane & 3);
        g_Cpk16[gid] = make_uint2(
            h2(g_C[(k0)     * HA + n], g_C[(k0 + 1) * HA + n]),
            h2(g_C[(k0 + 8) * HA + n], g_C[(k0 + 9) * HA + n]));
    } else if (gid < 8192) {
        // W2pk16: B = aW2 [256 k][64 d], index ((pass*8+na)*4+qa)*32+lane
        const int idx = gid - 4096;
        const int lane = idx & 31, qa = (idx >> 5) & 3, na = (idx >> 7) & 7, pass = idx >> 10;
        const int d  = 8 * na + (lane >> 2);
        const int k0 = 64 * pass + 16 * qa + 2 * (lane & 3);
        g_W2pk16[idx] = make_uint2(
            h2(aW2[(k0)     * DD + d], aW2[(k0 + 1) * DD + d]),
            h2(aW2[(k0 + 8) * DD + d], aW2[(k0 + 9) * DD + d]));
    } else if (gid < 9216) {
        // Ppk16: B = pW2 [64 c][64 d], index (na*4+ka)*32+lane
        const int idx = gid - 8192;
        const int lane = idx & 31, ka = (idx >> 5) & 3, na = idx >> 7;
        const int d  = 8 * na + (lane >> 2);
        const int k0 = 16 * ka + 2 * (lane & 3);
        g_Ppk16[idx] = make_uint2(
            h2(pW2[(k0)     * DD + d], pW2[(k0 + 1) * DD + d]),
            h2(pW2[(k0 + 8) * DD + d], pW2[(k0 + 9) * DD + d]));
    }
}

// ---------------- main fused kernel ----------------
// smem byte offsets
#define OFFB_CPK   0          // 32768  uint2 Cpk16
#define OFFB_W2PK  32768      // 32768  uint2 W2pk16
#define OFFB_PPK   65536      // 8192   uint2 Ppk16
#define OFFB_G     73728      // 36864  fp16 g tile [256 rows][72] (u32 stride 36)
#define OFFB_SCR   110592     // 36864  per-warp h scratch (32 x 72 fp16 each)
#define OFFB_BASE  147456     // 1024   f32 Base[256]
#define OFFB_PBI   148480     // 256    f32 Pbi[64]
#define OFFB_MX    148736     // 256    f32 running max
#define OFFB_F     148992     // 256    f32 rescale factor
#define OFFB_R1    149248     // 2048   8 warps x 64 staging
#define OFFB_R2    151296     // 2048
#define SMEM_BYTES 153344

__global__ __launch_bounds__(NT, 1)
void pt_main_kernel(const float* __restrict__ pb1,
                    const float* __restrict__ pb2,
                    float* __restrict__ out)
{
    extern __shared__ __align__(16) unsigned char smx[];
    uint2*    sCpk  = (uint2*)(smx + OFFB_CPK);
    uint2*    sW2pk = (uint2*)(smx + OFFB_W2PK);
    uint2*    sPpk  = (uint2*)(smx + OFFB_PPK);
    unsigned* sG    = (unsigned*)(smx + OFFB_G);     // u32 view of f16x2, 36 u32/row
    unsigned* sScrB = (unsigned*)(smx + OFFB_SCR);
    float*    sBase = (float*)(smx + OFFB_BASE);
    float*    sPbi  = (float*)(smx + OFFB_PBI);
    float*    sMx   = (float*)(smx + OFFB_MX);
    float*    sF    = (float*)(smx + OFFB_F);
    float*    sR1   = (float*)(smx + OFFB_R1);
    float*    sR2   = (float*)(smx + OFFB_R2);

    const int tid  = threadIdx.x;
    const int i    = blockIdx.x;
    const int w    = tid >> 5;
    const int lane = tid & 31;
    const int lrow = lane >> 2;     // 0..7
    const int t4   = lane & 3;      // 0..3
    const int R0   = 32 * w;        // warp's j-row base within tile (2 groups of 16)
    unsigned* sScr = sScrB + w * 1152;   // 32 rows x 36 u32

    // ---- load persistent packed weights + per-i state ----
    {
        const uint4* c4 = (const uint4*)g_Cpk16;
        const uint4* w4 = (const uint4*)g_W2pk16;
        const uint4* p4 = (const uint4*)g_Ppk16;
        uint4* sc = (uint4*)sCpk;
        uint4* sw = (uint4*)sW2pk;
        uint4* sp = (uint4*)sPpk;
#pragma unroll
        for (int r = 0; r < 8; ++r) {
            sc[tid + r * NT] = c4[tid + r * NT];
            sw[tid + r * NT] = w4[tid + r * NT];
        }
#pragma unroll
        for (int r = 0; r < 2; ++r) sp[tid + r * NT] = p4[tid + r * NT];
    }
    sBase[tid] = g_A[i * HA + tid];
    if (tid < DD) {
        sPbi[tid] = g_P[i * DD + tid] + pb1[tid];
        sMx[tid]  = -CUDART_INF_F;
    }
    __syncthreads();

    // per-thread channel-slot accumulators: slot (na,u) -> channel 8na+2t4+u
    float lacc[8][2], pacc[8][2];
#pragma unroll
    for (int na = 0; na < 8; ++na) {
        lacc[na][0] = lacc[na][1] = 0.f;
        pacc[na][0] = pacc[na][1] = 0.f;
    }

#pragma unroll 1
    for (int jt = 0; jt < NTILES; ++jt) {
        const int jb = jt * TJ;

        // ---- fill g tile fp16: g[j][c] = relu(Pbi[c] - P[jb+j][c]) ----
#pragma unroll 4
        for (int idx = tid; idx < TJ * 32; idx += NT) {
            const int row = idx >> 5, cp = idx & 31;
            const float2 pv = *(const float2*)&g_P[(jb + row) * DD + 2 * cp];
            const float2 pb = *(const float2*)&sPbi[2 * cp];
            sG[row * 36 + cp] = h2(fmaxf(pb.x - pv.x, 0.f), fmaxf(pb.y - pv.y, 0.f));
        }
        __syncthreads();

        // ---- A-fragments of g for both 16-row groups (k=64 -> 4 ka) ----
        unsigned ga[2][4][4];
#pragma unroll
        for (int gI = 0; gI < 2; ++gI)
#pragma unroll
            for (int ka = 0; ka < 4; ++ka) {
                const int rA = (R0 + 16 * gI + lrow) * 36;
                const int rB = (R0 + 16 * gI + lrow + 8) * 36;
                ga[gI][ka][0] = sG[rA + 8 * ka + t4];
                ga[gI][ka][1] = sG[rB + 8 * ka + t4];
                ga[gI][ka][2] = sG[rA + 8 * ka + t4 + 4];
                ga[gI][ka][3] = sG[rB + 8 * ka + t4 + 4];
            }

        float sim[2][8][4];
#pragma unroll
        for (int gI = 0; gI < 2; ++gI)
#pragma unroll
            for (int na = 0; na < 8; ++na)
#pragma unroll
                for (int u = 0; u < 4; ++u) sim[gI][na][u] = 0.f;

#pragma unroll 1
        for (int pass = 0; pass < 4; ++pass) {
            // GEMM1: h[32x64] = g @ C[:, pass*64 : +64] — B loaded ONCE for both groups
            float h[2][8][4];
#pragma unroll
            for (int gI = 0; gI < 2; ++gI)
#pragma unroll
                for (int na = 0; na < 8; ++na)
#pragma unroll
                    for (int u = 0; u < 4; ++u) h[gI][na][u] = 0.f;
#pragma unroll
            for (int ka = 0; ka < 4; ++ka)
#pragma unroll
                for (int na = 0; na < 8; ++na) {
                    const uint2 b = sCpk[((pass * 8 + na) * 4 + ka) * 32 + lane];
                    mma_f16(h[0][na], ga[0][ka], b.x, b.y);
                    mma_f16(h[1][na], ga[1][ka], b.x, b.y);
                }

            // epilogue: + Base - Bk, relu, -> fp16 scratch (both groups)
#pragma unroll
            for (int gI = 0; gI < 2; ++gI) {
                const int rowA = jb + R0 + 16 * gI + lrow;
#pragma unroll
                for (int na = 0; na < 8; ++na) {
                    const int col = 64 * pass + 8 * na + 2 * t4;
                    const float2 bs  = *(const float2*)&sBase[col];
                    const float2 bkA = *(const float2*)&g_Bk[rowA * HA + col];
                    const float2 bkB = *(const float2*)&g_Bk[(rowA + 8) * HA + col];
                    sScr[(16 * gI + lrow) * 36 + 4 * na + t4] =
                        h2(fmaxf(h[gI][na][0] + bs.x - bkA.x, 0.f),
                           fmaxf(h[gI][na][1] + bs.y - bkA.y, 0.f));
                    sScr[(16 * gI + lrow + 8) * 36 + 4 * na + t4] =
                        h2(fmaxf(h[gI][na][2] + bs.x - bkB.x, 0.f),
                           fmaxf(h[gI][na][3] + bs.y - bkB.y, 0.f));
                }
            }
            __syncwarp();

            // GEMM2: sim += relu(h) @ aW2[pass*64 : +64, :] — B loaded once per (qa,na)
#pragma unroll
            for (int qa = 0; qa < 4; ++qa) {
                unsigned a2[2][4];
#pragma unroll
                for (int gI = 0; gI < 2; ++gI) {
                    a2[gI][0] = sScr[(16 * gI + lrow) * 36 + 8 * qa + t4];
                    a2[gI][1] = sScr[(16 * gI + lrow + 8) * 36 + 8 * qa + t4];
                    a2[gI][2] = sScr[(16 * gI + lrow) * 36 + 8 * qa + t4 + 4];
                    a2[gI][3] = sScr[(16 * gI + lrow + 8) * 36 + 8 * qa + t4 + 4];
                }
#pragma unroll
                for (int na = 0; na < 8; ++na) {
                    const uint2 b = sW2pk[((pass * 8 + na) * 4 + qa) * 32 + lane];
                    mma_f16(sim[0][na], a2[0], b.x, b.y);
                    mma_f16(sim[1][na], a2[1], b.x, b.y);
                }
            }
            __syncwarp();
        }

        // ---- rpe GEMM: rp[32x64] = g @ pW2 (fragment layout == sim layout) ----
        float rp[2][8][4];
#pragma unroll
        for (int gI = 0; gI < 2; ++gI)
#pragma unroll
            for (int na = 0; na < 8; ++na)
#pragma unroll
                for (int u = 0; u < 4; ++u) rp[gI][na][u] = 0.f;
#pragma unroll
        for (int ka = 0; ka < 4; ++ka)
#pragma unroll
            for (int na = 0; na < 8; ++na) {
                const uint2 b = sPpk[(na * 4 + ka) * 32 + lane];
                mma_f16(rp[0][na], ga[0][ka], b.x, b.y);
                mma_f16(rp[1][na], ga[1][ka], b.x, b.y);
            }

        // ---- softmax: per-slot max over both groups -> shfl -> cross-warp ----
        float mx[8][2];
#pragma unroll
        for (int na = 0; na < 8; ++na) {
            mx[na][0] = fmaxf(fmaxf(sim[0][na][0], sim[0][na][2]),
                              fmaxf(sim[1][na][0], sim[1][na][2]));
            mx[na][1] = fmaxf(fmaxf(sim[0][na][1], sim[0][na][3]),
                              fmaxf(sim[1][na][1], sim[1][na][3]));
        }
#pragma unroll
        for (int off = 4; off < 32; off <<= 1)
#pragma unroll
            for (int na = 0; na < 8; ++na) {
                mx[na][0] = fmaxf(mx[na][0], __shfl_xor_sync(0xffffffffu, mx[na][0], off));
                mx[na][1] = fmaxf(mx[na][1], __shfl_xor_sync(0xffffffffu, mx[na][1], off));
            }
        if (lane < 4) {
#pragma unroll
            for (int na = 0; na < 8; ++na) {
                sR1[w * 64 + 8 * na + 2 * lane]     = mx[na][0];
                sR1[w * 64 + 8 * na + 2 * lane + 1] = mx[na][1];
            }
        }
        __syncthreads();

        if (tid < DD) {
            float gm = sR1[tid];
#pragma unroll
            for (int ww = 1; ww < 8; ++ww) gm = fmaxf(gm, sR1[ww * 64 + tid]);
            const float nm = fmaxf(gm, sMx[tid]);
            sF[tid]  = __expf(sMx[tid] - nm);
            sMx[tid] = nm;
        }
        __syncthreads();

        // ---- e + accumulate (registers), both groups ----
#pragma unroll
        for (int na = 0; na < 8; ++na) {
            const int ch = 8 * na + 2 * t4;
            const float2 nm2 = *(const float2*)&sMx[ch];
            const float2 f2v = *(const float2*)&sF[ch];
            float sl0 = 0.f, sl1 = 0.f, sp0 = 0.f, sp1 = 0.f;
#pragma unroll
            for (int gI = 0; gI < 2; ++gI) {
                const int rowA = jb + R0 + 16 * gI + lrow;
                const float2 vA = *(const float2*)&g_V[rowA * DD + ch];
                const float2 vB = *(const float2*)&g_V[(rowA + 8) * DD + ch];
                const float e00 = __expf(sim[gI][na][0] - nm2.x);
                const float e10 = __expf(sim[gI][na][2] - nm2.x);
                const float e01 = __expf(sim[gI][na][1] - nm2.y);
                const float e11 = __expf(sim[gI][na][3] - nm2.y);
                sl0 += e00 + e10;
                sl1 += e01 + e11;
                sp0 += e00 * (vA.x + rp[gI][na][0]) + e10 * (vB.x + rp[gI][na][2]);
                sp1 += e01 * (vA.y + rp[gI][na][1]) + e11 * (vB.y + rp[gI][na][3]);
            }
            lacc[na][0] = lacc[na][0] * f2v.x + sl0;
            lacc[na][1] = lacc[na][1] * f2v.y + sl1;
            pacc[na][0] = pacc[na][0] * f2v.x + sp0;
            pacc[na][1] = pacc[na][1] * f2v.y + sp1;
        }
        // next iteration's g-fill + its __syncthreads provide the hazard fence
    }

    // ---- final reduction: over lrow (shfl), then over warps (smem) ----
#pragma unroll
    for (int off = 4; off < 32; off <<= 1)
#pragma unroll
        for (int na = 0; na < 8; ++na) {
            lacc[na][0] += __shfl_xor_sync(0xffffffffu, lacc[na][0], off);
            lacc[na][1] += __shfl_xor_sync(0xffffffffu, lacc[na][1], off);
            pacc[na][0] += __shfl_xor_sync(0xffffffffu, pacc[na][0], off);
            pacc[na][1] += __shfl_xor_sync(0xffffffffu, pacc[na][1], off);
        }
    __syncthreads();
    if (lane < 4) {
#pragma unroll
        for (int na = 0; na < 8; ++na) {
            sR1[w * 64 + 8 * na + 2 * lane]     = lacc[na][0];
            sR1[w * 64 + 8 * na + 2 * lane + 1] = lacc[na][1];
            sR2[w * 64 + 8 * na + 2 * lane]     = pacc[na][0];
            sR2[w * 64 + 8 * na + 2 * lane + 1] = pacc[na][1];
        }
    }
    __syncthreads();
    if (tid < DD) {
        float L = 0.f, P = 0.f;
#pragma unroll
        for (int ww = 0; ww < 8; ++ww) {
            L += sR1[ww * 64 + tid];
            P += sR2[ww * 64 + tid];
        }
        out[i * DD + tid] = (P + L * pb2[tid]) / L;
    }
}

// ---------------- launch ----------------
extern "C" void kernel_launch(void* const* d_in, const int* in_sizes, int n_in,
                              void* d_out, int out_size)
{
    const float* x   = (const float*)d_in[0];
    const float* pos = (const float*)d_in[1];
    const float* Wq  = (const float*)d_in[2];
    const float* Wk  = (const float*)d_in[3];
    const float* Wv  = (const float*)d_in[4];
    const float* pW1 = (const float*)d_in[5];
    const float* pb1 = (const float*)d_in[6];
    const float* pW2 = (const float*)d_in[7];
    const float* pb2 = (const float*)d_in[8];
    const float* aW1 = (const float*)d_in[9];
    const float* ab1 = (const float*)d_in[10];
    const float* aW2 = (const float*)d_in[11];
    // ab2 constant over j -> cancels in per-channel softmax
    float* out = (float*)d_out;

    cudaFuncSetAttribute(pt_main_kernel,
                         cudaFuncAttributeMaxDynamicSharedMemorySize, SMEM_BYTES);

    pt_proj_kernel<<<NPTS / 4, NT>>>(x, pos, Wq, Wk, Wv, pW1, pb2, aW1, ab1);
    pt_cmat_kernel<<<DD, HA>>>(pW2, aW1);
    pt_pack16_kernel<<<36, NT>>>(aW2, pW2);
    pt_main_kernel<<<NPTS, NT, SMEM_BYTES>>>(pb1, pb2, out);
}

// round 12
// speedup vs baseline: 5.7138x; 1.0550x over previous
#include <cuda_runtime.h>
#include <cuda_fp16.h>
#include <math_constants.h>

#define NPTS 1024
#define DD   64
#define HA   256
#define TJ   256     // j-rows per tile (32 per warp x 8 warps)
#define NT   256
#define NTILES (NPTS / TJ)

// ---------------- device scratch ----------------
__device__ float g_P [NPTS * DD];    // pos @ pW1
__device__ float g_A [NPTS * HA];    // (q + pb2) @ aW1 + ab1
__device__ float g_Bk[NPTS * HA];    // k @ aW1 (f32, packed to f16 below)
__device__ float g_V [NPTS * DD];    // v
__device__ float g_C [DD * HA];      // pW2 @ aW1
__device__ unsigned g_BkH[NPTS * HA / 2];  // Bk as f16x2 row-major
__device__ uint2 g_Cpk16 [4096];     // C packed as fp16 B-fragments
__device__ uint2 g_W2pk16[4096];     // aW2 packed fp16 B-fragments
__device__ uint2 g_Ppk16 [1024];     // pW2 packed fp16 B-fragments

// ---------------- helpers ----------------
__device__ __forceinline__ unsigned h2(float lo, float hi) {
    unsigned r;
    asm("cvt.rn.f16x2.f32 %0, %1, %2;" : "=r"(r) : "f"(hi), "f"(lo));  // first src -> upper half
    return r;
}
__device__ __forceinline__ void mma_f16(float* d, const unsigned* a,
                                        unsigned b0, unsigned b1) {
    asm volatile(
        "mma.sync.aligned.m16n8k16.row.col.f32.f16.f16.f32 "
        "{%0,%1,%2,%3}, {%4,%5,%6,%7}, {%8,%9}, {%0,%1,%2,%3};"
        : "+f"(d[0]), "+f"(d[1]), "+f"(d[2]), "+f"(d[3])
        : "r"(a[0]), "r"(a[1]), "r"(a[2]), "r"(a[3]), "r"(b0), "r"(b1));
}

// ---------------- kernel 1: per-point projections (4 pts/block) ----------------
__global__ void pt_proj_kernel(const float* __restrict__ x,
                               const float* __restrict__ pos,
                               const float* __restrict__ Wq,
                               const float* __restrict__ Wk,
                               const float* __restrict__ Wv,
                               const float* __restrict__ pW1,
                               const float* __restrict__ pb2,
                               const float* __restrict__ aW1,
                               const float* __restrict__ ab1)
{
    __shared__ float sx[4][DD], sq[4][DD], sk[4][DD];
    const int tid = threadIdx.x;
    const int pt  = tid >> 6;
    const int d   = tid & 63;
    const int i   = blockIdx.x * 4 + pt;

    sx[pt][d] = x[i * DD + d];
    __syncthreads();

    float q = 0.f, k = 0.f, v = 0.f;
#pragma unroll 8
    for (int c = 0; c < DD; ++c) {
        const float xc = sx[pt][c];
        q = fmaf(xc, Wq[c * DD + d], q);
        k = fmaf(xc, Wk[c * DD + d], k);
        v = fmaf(xc, Wv[c * DD + d], v);
    }
    g_P[i * DD + d] = pos[i * 2] * pW1[d] + pos[i * 2 + 1] * pW1[DD + d];
    g_V[i * DD + d] = v;
    sq[pt][d] = q + pb2[d];
    sk[pt][d] = k;
    __syncthreads();

    const int n = tid;
    float A0 = ab1[n], A1 = A0, A2 = A0, A3 = A0;
    float B0 = 0.f, B1 = 0.f, B2 = 0.f, B3 = 0.f;
#pragma unroll 8
    for (int c = 0; c < DD; ++c) {
        const float w = aW1[c * HA + n];
        A0 = fmaf(sq[0][c], w, A0); B0 = fmaf(sk[0][c], w, B0);
        A1 = fmaf(sq[1][c], w, A1); B1 = fmaf(sk[1][c], w, B1);
        A2 = fmaf(sq[2][c], w, A2); B2 = fmaf(sk[2][c], w, B2);
        A3 = fmaf(sq[3][c], w, A3); B3 = fmaf(sk[3][c], w, B3);
    }
    const int ib = blockIdx.x * 4;
    g_A [(ib + 0) * HA + n] = A0;  g_Bk[(ib + 0) * HA + n] = B0;
    g_A [(ib + 1) * HA + n] = A1;  g_Bk[(ib + 1) * HA + n] = B1;
    g_A [(ib + 2) * HA + n] = A2;  g_Bk[(ib + 2) * HA + n] = B2;
    g_A [(ib + 3) * HA + n] = A3;  g_Bk[(ib + 3) * HA + n] = B3;
}

// ---------------- kernel 2: C = pW2 @ aW1 ----------------
__global__ void pt_cmat_kernel(const float* __restrict__ pW2,
                               const float* __restrict__ aW1)
{
    const int c = blockIdx.x;
    const int n = threadIdx.x;
    float acc = 0.f;
#pragma unroll 8
    for (int d = 0; d < DD; ++d)
        acc = fmaf(pW2[c * DD + d], aW1[d * HA + n], acc);
    g_C[c * HA + n] = acc;
}

// ---------------- kernel 2b: pack Bk -> f16x2 row-major ----------------
__global__ void pt_packbk_kernel()
{
    const int gid = blockIdx.x * blockDim.x + threadIdx.x;  // 0..131071
    const int row = gid >> 7, c2 = gid & 127;
    g_BkH[gid] = h2(g_Bk[row * HA + 2 * c2], g_Bk[row * HA + 2 * c2 + 1]);
}

// ---------------- kernel 3: pack fp16 B-fragments ----------------
// m16n8k16 B layout: b0 = {B[k0+2t][n], B[k0+2t+1][n]}, b1 = {B[k0+2t+8][n], B[k0+2t+9][n]}
__global__ void pt_pack16_kernel(const float* __restrict__ aW2,
                                 const float* __restrict__ pW2)
{
    const int gid = blockIdx.x * blockDim.x + threadIdx.x;
    if (gid < 4096) {
        // Cpk16: B = C [64 c][256 n], index ((pass*8+na)*4+ka)*32+lane
        const int lane = gid & 31, ka = (gid >> 5) & 3, na = (gid >> 7) & 7, pass = gid >> 10;
        const int n  = 64 * pass + 8 * na + (lane >> 2);
        const int k0 = 16 * ka + 2 * (lane & 3);
        g_Cpk16[gid] = make_uint2(
            h2(g_C[(k0)     * HA + n], g_C[(k0 + 1) * HA + n]),
            h2(g_C[(k0 + 8) * HA + n], g_C[(k0 + 9) * HA + n]));
    } else if (gid < 8192) {
        // W2pk16: B = aW2 [256 k][64 d], index ((pass*8+na)*4+qa)*32+lane
        const int idx = gid - 4096;
        const int lane = idx & 31, qa = (idx >> 5) & 3, na = (idx >> 7) & 7, pass = idx >> 10;
        const int d  = 8 * na + (lane >> 2);
        const int k0 = 64 * pass + 16 * qa + 2 * (lane & 3);
        g_W2pk16[idx] = make_uint2(
            h2(aW2[(k0)     * DD + d], aW2[(k0 + 1) * DD + d]),
            h2(aW2[(k0 + 8) * DD + d], aW2[(k0 + 9) * DD + d]));
    } else if (gid < 9216) {
        // Ppk16: B = pW2 [64 c][64 d], index (na*4+ka)*32+lane
        const int idx = gid - 8192;
        const int lane = idx & 31, ka = (idx >> 5) & 3, na = idx >> 7;
        const int d  = 8 * na + (lane >> 2);
        const int k0 = 16 * ka + 2 * (lane & 3);
        g_Ppk16[idx] = make_uint2(
            h2(pW2[(k0)     * DD + d], pW2[(k0 + 1) * DD + d]),
            h2(pW2[(k0 + 8) * DD + d], pW2[(k0 + 9) * DD + d]));
    }
}

// ---------------- main fused kernel ----------------
// smem byte offsets (scratch region REMOVED: h never leaves registers)
#define OFFB_CPK   0          // 32768  uint2 Cpk16
#define OFFB_W2PK  32768      // 32768  uint2 W2pk16
#define OFFB_PPK   65536      // 8192   uint2 Ppk16
#define OFFB_G     73728      // 36864  fp16 g tile [256 rows][72] (u32 stride 36)
#define OFFB_BASE  110592     // 1024   f32 Base[256]
#define OFFB_PBI   111616     // 256    f32 Pbi[64]
#define OFFB_MX    111872     // 256    f32 running max
#define OFFB_F     112128     // 256    f32 rescale factor
#define OFFB_R1    112384     // 2048   8 warps x 64 staging
#define OFFB_R2    114432     // 2048
#define SMEM_BYTES 116480

__global__ __launch_bounds__(NT, 1)
void pt_main_kernel(const float* __restrict__ pb1,
                    const float* __restrict__ pb2,
                    float* __restrict__ out)
{
    extern __shared__ __align__(16) unsigned char smx[];
    uint2*    sCpk  = (uint2*)(smx + OFFB_CPK);
    uint2*    sW2pk = (uint2*)(smx + OFFB_W2PK);
    uint2*    sPpk  = (uint2*)(smx + OFFB_PPK);
    unsigned* sG    = (unsigned*)(smx + OFFB_G);     // u32 view of f16x2, 36 u32/row
    float*    sBase = (float*)(smx + OFFB_BASE);
    float*    sPbi  = (float*)(smx + OFFB_PBI);
    float*    sMx   = (float*)(smx + OFFB_MX);
    float*    sF    = (float*)(smx + OFFB_F);
    float*    sR1   = (float*)(smx + OFFB_R1);
    float*    sR2   = (float*)(smx + OFFB_R2);

    const int tid  = threadIdx.x;
    const int i    = blockIdx.x;
    const int w    = tid >> 5;
    const int lane = tid & 31;
    const int lrow = lane >> 2;     // 0..7
    const int t4   = lane & 3;      // 0..3
    const int R0   = 32 * w;        // warp's j-row base within tile (2 groups of 16)

    // ---- load persistent packed weights + per-i state ----
    {
        const uint4* c4 = (const uint4*)g_Cpk16;
        const uint4* w4 = (const uint4*)g_W2pk16;
        const uint4* p4 = (const uint4*)g_Ppk16;
        uint4* sc = (uint4*)sCpk;
        uint4* sw = (uint4*)sW2pk;
        uint4* sp = (uint4*)sPpk;
#pragma unroll
        for (int r = 0; r < 8; ++r) {
            sc[tid + r * NT] = c4[tid + r * NT];
            sw[tid + r * NT] = w4[tid + r * NT];
        }
#pragma unroll
        for (int r = 0; r < 2; ++r) sp[tid + r * NT] = p4[tid + r * NT];
    }
    sBase[tid] = g_A[i * HA + tid];
    if (tid < DD) {
        sPbi[tid] = g_P[i * DD + tid] + pb1[tid];
        sMx[tid]  = -CUDART_INF_F;
    }
    __syncthreads();

    // per-thread channel-slot accumulators: slot (na,u) -> channel 8na+2t4+u
    float lacc[8][2], pacc[8][2];
#pragma unroll
    for (int na = 0; na < 8; ++na) {
        lacc[na][0] = lacc[na][1] = 0.f;
        pacc[na][0] = pacc[na][1] = 0.f;
    }

#pragma unroll 1
    for (int jt = 0; jt < NTILES; ++jt) {
        const int jb = jt * TJ;

        // ---- fill g tile fp16: g[j][c] = relu(Pbi[c] - P[jb+j][c]) ----
#pragma unroll 4
        for (int idx = tid; idx < TJ * 32; idx += NT) {
            const int row = idx >> 5, cp = idx & 31;
            const float2 pv = *(const float2*)&g_P[(jb + row) * DD + 2 * cp];
            const float2 pb = *(const float2*)&sPbi[2 * cp];
            sG[row * 36 + cp] = h2(fmaxf(pb.x - pv.x, 0.f), fmaxf(pb.y - pv.y, 0.f));
        }
        __syncthreads();

        // ---- A-fragments of g for both 16-row groups (k=64 -> 4 ka) ----
        unsigned ga[2][4][4];
#pragma unroll
        for (int gI = 0; gI < 2; ++gI)
#pragma unroll
            for (int ka = 0; ka < 4; ++ka) {
                const int rA = (R0 + 16 * gI + lrow) * 36;
                const int rB = (R0 + 16 * gI + lrow + 8) * 36;
                ga[gI][ka][0] = sG[rA + 8 * ka + t4];
                ga[gI][ka][1] = sG[rB + 8 * ka + t4];
                ga[gI][ka][2] = sG[rA + 8 * ka + t4 + 4];
                ga[gI][ka][3] = sG[rB + 8 * ka + t4 + 4];
            }

        float sim[2][8][4];
#pragma unroll
        for (int gI = 0; gI < 2; ++gI)
#pragma unroll
            for (int na = 0; na < 8; ++na)
#pragma unroll
                for (int u = 0; u < 4; ++u) sim[gI][na][u] = 0.f;

#pragma unroll 1
        for (int pass = 0; pass < 4; ++pass) {
#pragma unroll
            for (int ka2 = 0; ka2 < 4; ++ka2) {
                // GEMM1 for na pair (2ka2, 2ka2+1), both row groups
                float hh[2][2][4];
#pragma unroll
                for (int gI = 0; gI < 2; ++gI)
#pragma unroll
                    for (int p = 0; p < 2; ++p)
#pragma unroll
                        for (int u = 0; u < 4; ++u) hh[gI][p][u] = 0.f;
#pragma unroll
                for (int ka = 0; ka < 4; ++ka) {
                    const uint2 b0 = sCpk[((pass * 8 + 2 * ka2)     * 4 + ka) * 32 + lane];
                    mma_f16(hh[0][0], ga[0][ka], b0.x, b0.y);
                    mma_f16(hh[1][0], ga[1][ka], b0.x, b0.y);
                    const uint2 b1 = sCpk[((pass * 8 + 2 * ka2 + 1) * 4 + ka) * 32 + lane];
                    mma_f16(hh[0][1], ga[0][ka], b1.x, b1.y);
                    mma_f16(hh[1][1], ga[1][ka], b1.x, b1.y);
                }

                // epilogue in registers: + Base - Bk(f16), relu, pack directly
                // into GEMM2 A-fragments (C-frag == A-frag layout identity)
                unsigned afr[2][4];
#pragma unroll
                for (int gI = 0; gI < 2; ++gI) {
                    const int rowA = jb + R0 + 16 * gI + lrow;
#pragma unroll
                    for (int p = 0; p < 2; ++p) {
                        const int na  = 2 * ka2 + p;
                        const int col = 64 * pass + 8 * na + 2 * t4;
                        const float2 bs = *(const float2*)&sBase[col];
                        const unsigned bkAu = g_BkH[rowA * (HA / 2) + (col >> 1)];
                        const unsigned bkBu = g_BkH[(rowA + 8) * (HA / 2) + (col >> 1)];
                        const float2 bkA = __half22float2(*(const __half2*)&bkAu);
                        const float2 bkB = __half22float2(*(const __half2*)&bkBu);
                        const float x0 = fmaxf(hh[gI][p][0] + bs.x - bkA.x, 0.f);
                        const float x1 = fmaxf(hh[gI][p][1] + bs.y - bkA.y, 0.f);
                        const float x2 = fmaxf(hh[gI][p][2] + bs.x - bkB.x, 0.f);
                        const float x3 = fmaxf(hh[gI][p][3] + bs.y - bkB.y, 0.f);
                        afr[gI][2 * p]     = h2(x0, x1);
                        afr[gI][2 * p + 1] = h2(x2, x3);
                    }
                }

                // GEMM2: sim += relu(h) @ aW2, k-group = (pass, ka2)
#pragma unroll
                for (int na2 = 0; na2 < 8; ++na2) {
                    const uint2 b = sW2pk[((pass * 8 + na2) * 4 + ka2) * 32 + lane];
                    mma_f16(sim[0][na2], afr[0], b.x, b.y);
                    mma_f16(sim[1][na2], afr[1], b.x, b.y);
                }
            }
        }

        // ---- rpe GEMM: rp[32x64] = g @ pW2 (fragment layout == sim layout) ----
        float rp[2][8][4];
#pragma unroll
        for (int gI = 0; gI < 2; ++gI)
#pragma unroll
            for (int na = 0; na < 8; ++na)
#pragma unroll
                for (int u = 0; u < 4; ++u) rp[gI][na][u] = 0.f;
#pragma unroll
        for (int ka = 0; ka < 4; ++ka)
#pragma unroll
            for (int na = 0; na < 8; ++na) {
                const uint2 b = sPpk[(na * 4 + ka) * 32 + lane];
                mma_f16(rp[0][na], ga[0][ka], b.x, b.y);
                mma_f16(rp[1][na], ga[1][ka], b.x, b.y);
            }

        // ---- softmax: per-slot max over both groups -> shfl -> cross-warp ----
        float mx[8][2];
#pragma unroll
        for (int na = 0; na < 8; ++na) {
            mx[na][0] = fmaxf(fmaxf(sim[0][na][0], sim[0][na][2]),
                              fmaxf(sim[1][na][0], sim[1][na][2]));
            mx[na][1] = fmaxf(fmaxf(sim[0][na][1], sim[0][na][3]),
                              fmaxf(sim[1][na][1], sim[1][na][3]));
        }
#pragma unroll
        for (int off = 4; off < 32; off <<= 1)
#pragma unroll
            for (int na = 0; na < 8; ++na) {
                mx[na][0] = fmaxf(mx[na][0], __shfl_xor_sync(0xffffffffu, mx[na][0], off));
                mx[na][1] = fmaxf(mx[na][1], __shfl_xor_sync(0xffffffffu, mx[na][1], off));
            }
        if (lane < 4) {
#pragma unroll
            for (int na = 0; na < 8; ++na) {
                sR1[w * 64 + 8 * na + 2 * lane]     = mx[na][0];
                sR1[w * 64 + 8 * na + 2 * lane + 1] = mx[na][1];
            }
        }
        __syncthreads();

        if (tid < DD) {
            float gm = sR1[tid];
#pragma unroll
            for (int ww = 1; ww < 8; ++ww) gm = fmaxf(gm, sR1[ww * 64 + tid]);
            const float nm = fmaxf(gm, sMx[tid]);
            sF[tid]  = __expf(sMx[tid] - nm);
            sMx[tid] = nm;
        }
        __syncthreads();

        // ---- e + accumulate (registers), both groups ----
#pragma unroll
        for (int na = 0; na < 8; ++na) {
            const int ch = 8 * na + 2 * t4;
            const float2 nm2 = *(const float2*)&sMx[ch];
            const float2 f2v = *(const float2*)&sF[ch];
            float sl0 = 0.f, sl1 = 0.f, sp0 = 0.f, sp1 = 0.f;
#pragma unroll
            for (int gI = 0; gI < 2; ++gI) {
                const int rowA = jb + R0 + 16 * gI + lrow;
                const float2 vA = *(const float2*)&g_V[rowA * DD + ch];
                const float2 vB = *(const float2*)&g_V[(rowA + 8) * DD + ch];
                const float e00 = __expf(sim[gI][na][0] - nm2.x);
                const float e10 = __expf(sim[gI][na][2] - nm2.x);
                const float e01 = __expf(sim[gI][na][1] - nm2.y);
                const float e11 = __expf(sim[gI][na][3] - nm2.y);
                sl0 += e00 + e10;
                sl1 += e01 + e11;
                sp0 += e00 * (vA.x + rp[gI][na][0]) + e10 * (vB.x + rp[gI][na][2]);
                sp1 += e01 * (vA.y + rp[gI][na][1]) + e11 * (vB.y + rp[gI][na][3]);
            }
            lacc[na][0] = lacc[na][0] * f2v.x + sl0;
            lacc[na][1] = lacc[na][1] * f2v.y + sl1;
            pacc[na][0] = pacc[na][0] * f2v.x + sp0;
            pacc[na][1] = pacc[na][1] * f2v.y + sp1;
        }
        // next iteration's g-fill + its __syncthreads provide the hazard fence
    }

    // ---- final reduction: over lrow (shfl), then over warps (smem) ----
#pragma unroll
    for (int off = 4; off < 32; off <<= 1)
#pragma unroll
        for (int na = 0; na < 8; ++na) {
            lacc[na][0] += __shfl_xor_sync(0xffffffffu, lacc[na][0], off);
            lacc[na][1] += __shfl_xor_sync(0xffffffffu, lacc[na][1], off);
            pacc[na][0] += __shfl_xor_sync(0xffffffffu, pacc[na][0], off);
            pacc[na][1] += __shfl_xor_sync(0xffffffffu, pacc[na][1], off);
        }
    __syncthreads();
    if (lane < 4) {
#pragma unroll
        for (int na = 0; na < 8; ++na) {
            sR1[w * 64 + 8 * na + 2 * lane]     = lacc[na][0];
            sR1[w * 64 + 8 * na + 2 * lane + 1] = lacc[na][1];
            sR2[w * 64 + 8 * na + 2 * lane]     = pacc[na][0];
            sR2[w * 64 + 8 * na + 2 * lane + 1] = pacc[na][1];
        }
    }
    __syncthreads();
    if (tid < DD) {
        float L = 0.f, P = 0.f;
#pragma unroll
        for (int ww = 0; ww < 8; ++ww) {
            L += sR1[ww * 64 + tid];
            P += sR2[ww * 64 + tid];
        }
        out[i * DD + tid] = (P + L * pb2[tid]) / L;
    }
}

// ---------------- launch ----------------
extern "C" void kernel_launch(void* const* d_in, const int* in_sizes, int n_in,
                              void* d_out, int out_size)
{
    const float* x   = (const float*)d_in[0];
    const float* pos = (const float*)d_in[1];
    const float* Wq  = (const float*)d_in[2];
    const float* Wk  = (const float*)d_in[3];
    const float* Wv  = (const float*)d_in[4];
    const float* pW1 = (const float*)d_in[5];
    const float* pb1 = (const float*)d_in[6];
    const float* pW2 = (const float*)d_in[7];
    const float* pb2 = (const float*)d_in[8];
    const float* aW1 = (const float*)d_in[9];
    const float* ab1 = (const float*)d_in[10];
    const float* aW2 = (const float*)d_in[11];
    // ab2 constant over j -> cancels in per-channel softmax
    float* out = (float*)d_out;

    cudaFuncSetAttribute(pt_main_kernel,
                         cudaFuncAttributeMaxDynamicSharedMemorySize, SMEM_BYTES);

    pt_proj_kernel<<<NPTS / 4, NT>>>(x, pos, Wq, Wk, Wv, pW1, pb2, aW1, ab1);
    pt_cmat_kernel<<<DD, HA>>>(pW2, aW1);
    pt_packbk_kernel<<<NPTS * HA / 2 / NT, NT>>>();
    pt_pack16_kernel<<<36, NT>>>(aW2, pW2);
    pt_main_kernel<<<NPTS, NT, SMEM_BYTES>>>(pb1, pb2, out);
}